// round 11
// baseline (speedup 1.0000x reference)
#include <cuda_runtime.h>
#include <cuda_bf16.h>
#include <stdint.h>
#include <math.h>

#define MAXN 50000
#define MAXE 800000
#define NF 256

// ---------------- scratch (device globals; no allocation allowed) ----------
__device__ float g_h[(size_t)MAXN * NF];     // GEMM fp32 output (for agg gather)
__device__ float g_alpha[(size_t)6 * MAXN * 4];
__device__ float g_wexp[(size_t)MAXE * 4];
__device__ int   g_cnt[MAXN];
__device__ int   g_rowptr[MAXN + 1];
__device__ int   g_cursor[MAXN];
__device__ int   g_colsrc[MAXE];
__device__ int   g_coldst[MAXE];
// pre-split activations: [row][kpair] packed bf16x2
__device__ uint32_t g_xh[(size_t)MAXN * 256], g_xl[(size_t)MAXN * 256];   // x: K=512
__device__ uint32_t g_yh[(size_t)MAXN * 128], g_yl[(size_t)MAXN * 128];   // layer outs: K=256
// pre-transposed, bf16-split weights: [n][kpair] packed bf16x2
__device__ uint32_t g_w0h[256 * 256], g_w0l[256 * 256];
__device__ uint32_t g_w1h[256 * 128], g_w1l[256 * 128];
__device__ uint32_t g_w2h[256 * 128], g_w2l[256 * 128];

// ---------------- bf16 split helpers ----------------------------------------
__device__ __forceinline__ uint32_t bf16_pack_hi(float f0, float f1) {
    __nv_bfloat16 h0 = __float2bfloat16(f0);
    __nv_bfloat16 h1 = __float2bfloat16(f1);
    return (uint32_t)__bfloat16_as_ushort(h0) | ((uint32_t)__bfloat16_as_ushort(h1) << 16);
}
__device__ __forceinline__ uint32_t bf16_pack_lo(float f0, float f1) {
    __nv_bfloat16 h0 = __float2bfloat16(f0);
    __nv_bfloat16 h1 = __float2bfloat16(f1);
    __nv_bfloat16 l0 = __float2bfloat16(f0 - __bfloat162float(h0));
    __nv_bfloat16 l1 = __float2bfloat16(f1 - __bfloat162float(h1));
    return (uint32_t)__bfloat16_as_ushort(l0) | ((uint32_t)__bfloat16_as_ushort(l1) << 16);
}

__device__ __forceinline__ void mma_bf16(float c[4],
                                         uint32_t a0, uint32_t a1, uint32_t a2, uint32_t a3,
                                         uint32_t b0, uint32_t b1) {
    asm volatile(
        "mma.sync.aligned.m16n8k16.row.col.f32.bf16.bf16.f32 "
        "{%0,%1,%2,%3}, {%4,%5,%6,%7}, {%8,%9}, {%0,%1,%2,%3};"
        : "+f"(c[0]), "+f"(c[1]), "+f"(c[2]), "+f"(c[3])
        : "r"(a0), "r"(a1), "r"(a2), "r"(a3), "r"(b0), "r"(b1));
}

// ---------------- x pre-split: fp32 -> bf16 hi/lo ----------------------------
__global__ void prep_x_kernel(const float2* __restrict__ x2,
                              uint32_t* __restrict__ xh, uint32_t* __restrict__ xl,
                              int total) {
    int t = blockIdx.x * blockDim.x + threadIdx.x;
    if (t < total) {
        float2 f = x2[t];                 // row*512 + 2*kp == 2*t (contiguous)
        xh[t] = bf16_pack_hi(f.x, f.y);
        xl[t] = bf16_pack_lo(f.x, f.y);
    }
}

// ---------------- hist + weight prep + alpha zero (fused) --------------------
__global__ void hist_kernel(const int* __restrict__ dst, int* __restrict__ cnt, int e,
                            float* __restrict__ alpha,
                            const float* __restrict__ W0, const float* __restrict__ W1,
                            const float* __restrict__ W2,
                            uint32_t* __restrict__ w0h, uint32_t* __restrict__ w0l,
                            uint32_t* __restrict__ w1h, uint32_t* __restrict__ w1l,
                            uint32_t* __restrict__ w2h, uint32_t* __restrict__ w2l) {
    int t = blockIdx.x * blockDim.x + threadIdx.x;
    if (t < e) atomicAdd(&cnt[dst[t]], 1);
    // zero alpha accumulators (GEMM epilogue atomically accumulates into them;
    // REQUIRED for graph-replay determinism)
    const int atot = 6 * MAXN * 4;
    for (int i = t; i < atot; i += gridDim.x * blockDim.x) alpha[i] = 0.f;
    const int T0 = 256 * 256, T1 = 256 * 128;
    if (t < T0) {
        int n = t >> 8, kp = t & 255;
        float f0 = W0[(2 * kp) * 256 + n];
        float f1 = W0[(2 * kp + 1) * 256 + n];
        w0h[n * 256 + kp] = bf16_pack_hi(f0, f1);
        w0l[n * 256 + kp] = bf16_pack_lo(f0, f1);
    } else if (t < T0 + T1) {
        int id = t - T0;
        int n = id >> 7, kp = id & 127;
        float f0 = W1[(2 * kp) * 256 + n];
        float f1 = W1[(2 * kp + 1) * 256 + n];
        w1h[n * 128 + kp] = bf16_pack_hi(f0, f1);
        w1l[n * 128 + kp] = bf16_pack_lo(f0, f1);
    } else if (t < T0 + 2 * T1) {
        int id = t - T0 - T1;
        int n = id >> 7, kp = id & 127;
        float f0 = W2[(2 * kp) * 256 + n];
        float f1 = W2[(2 * kp + 1) * 256 + n];
        w2h[n * 128 + kp] = bf16_pack_hi(f0, f1);
        w2l[n * 128 + kp] = bf16_pack_lo(f0, f1);
    }
}

__global__ void scan_kernel(int* __restrict__ cnt, int* __restrict__ rowptr,
                            int* __restrict__ cursor, int n) {
    __shared__ int sh[1024];
    int tid = threadIdx.x;
    int chunk = (n + 1023) >> 10;
    int base = tid * chunk;
    int s = 0;
    for (int j = 0; j < chunk; j++) {
        int idx = base + j;
        if (idx < n) s += cnt[idx];
    }
    sh[tid] = s;
    __syncthreads();
    for (int off = 1; off < 1024; off <<= 1) {
        int v = (tid >= off) ? sh[tid - off] : 0;
        __syncthreads();
        sh[tid] += v;
        __syncthreads();
    }
    int run = sh[tid] - s;
    for (int j = 0; j < chunk; j++) {
        int idx = base + j;
        if (idx < n) {
            rowptr[idx] = run;
            cursor[idx] = run;
            run += cnt[idx];
            cnt[idx] = 0;
        }
    }
    if (tid == 1023) rowptr[n] = run;
}

__global__ void scatter_kernel(const int* __restrict__ src, const int* __restrict__ dst,
                               int* __restrict__ cursor, int* __restrict__ colsrc,
                               int* __restrict__ coldst, int e) {
    int t = blockIdx.x * blockDim.x + threadIdx.x;
    if (t < e) {
        int d = dst[t];
        int p = atomicAdd(&cursor[d], 1);
        colsrc[p] = src[t];
        coldst[p] = d;
    }
}

// ---------------- per-edge softmax numerators --------------------------------
template <int H>
__global__ void weight_kernel(const float* __restrict__ asrc, const float* __restrict__ adst,
                              const int* __restrict__ colsrc, const int* __restrict__ coldst,
                              float* __restrict__ wexp, int e) {
    int t = blockIdx.x * blockDim.x + threadIdx.x;
    if (t < e) {
        int s = colsrc[t], d = coldst[t];
#pragma unroll
        for (int h = 0; h < H; h++) {
            float ev = asrc[s * H + h] + adst[d * H + h];
            ev = ev > 0.f ? ev : 0.2f * ev;
            wexp[t * H + h] = __expf(ev);
        }
    }
}

// ---------------- bf16x3 tensor-core GEMM + fused alpha projection ----------
// C[M,256] = A[M,K] @ B[K,256]; BOTH operands pre-split [major][kpair] bf16x2.
// 128x128 CTA tile, BK=32, 8 warps (2x4), warp tile 64x32, m16n8k16 bf16 mma,
// 3-term split (hi*hi + hi*lo + lo*hi). Mainloop has no conversions.
template <int H>
__global__ void __launch_bounds__(256, 2) gemm_bf16(
    const uint32_t* __restrict__ Ath, const uint32_t* __restrict__ Atl,
    const uint32_t* __restrict__ Bth, const uint32_t* __restrict__ Btl,
    float* __restrict__ C, int M, int K,
    const float* __restrict__ a_s, const float* __restrict__ a_d,
    float* __restrict__ asrc, float* __restrict__ adst)
{
    __shared__ uint32_t Ah[128 * 20];
    __shared__ uint32_t Al[128 * 20];
    __shared__ uint32_t Bh[128 * 20];
    __shared__ uint32_t Bl[128 * 20];

    const int tid  = threadIdx.x;
    const int lane = tid & 31;
    const int w    = tid >> 5;
    const int g    = lane >> 2;
    const int t    = lane & 3;
    const int wm   = w >> 2;
    const int wn   = w & 3;

    const int row0 = blockIdx.y * 128;
    const int col0 = blockIdx.x * 128;
    const int KW   = K >> 1;

    // staging indices: each thread stages 16 kpairs of one row (2x uint4)
    const int ar  = tid >> 1;
    const int ak8 = (tid & 1) << 3;
    const bool a_ok = (row0 + ar) < M;

    const uint32_t* Ahrow = Ath + (size_t)(row0 + ar) * KW + ak8;
    const uint32_t* Alrow = Atl + (size_t)(row0 + ar) * KW + ak8;
    const uint32_t* Bhrow = Bth + (size_t)(col0 + ar) * KW + ak8;
    const uint32_t* Blrow = Btl + (size_t)(col0 + ar) * KW + ak8;

    float acc[4][4][4];
#pragma unroll
    for (int mt = 0; mt < 4; mt++)
#pragma unroll
        for (int nt = 0; nt < 4; nt++)
#pragma unroll
            for (int i = 0; i < 4; i++) acc[mt][nt][i] = 0.f;

    const uint4 z4 = make_uint4(0u, 0u, 0u, 0u);
    uint4 pah0, pah1, pal0, pal1, pbh0, pbh1, pbl0, pbl1;

    // prefetch tile 0
    pah0 = a_ok ? *(const uint4*)(Ahrow)     : z4;
    pah1 = a_ok ? *(const uint4*)(Ahrow + 4) : z4;
    pal0 = a_ok ? *(const uint4*)(Alrow)     : z4;
    pal1 = a_ok ? *(const uint4*)(Alrow + 4) : z4;
    pbh0 = *(const uint4*)(Bhrow);
    pbh1 = *(const uint4*)(Bhrow + 4);
    pbl0 = *(const uint4*)(Blrow);
    pbl1 = *(const uint4*)(Blrow + 4);

    for (int kt = 0; kt < K; kt += 32) {
        // ---- store staged tile (pure copies) ----
        {
            uint32_t* pA  = &Ah[ar * 20 + ak8];
            uint32_t* pAl = &Al[ar * 20 + ak8];
            uint32_t* pB  = &Bh[ar * 20 + ak8];
            uint32_t* pBl = &Bl[ar * 20 + ak8];
            *(uint4*)(pA)      = pah0;
            *(uint4*)(pA + 4)  = pah1;
            *(uint4*)(pAl)     = pal0;
            *(uint4*)(pAl + 4) = pal1;
            *(uint4*)(pB)      = pbh0;
            *(uint4*)(pB + 4)  = pbh1;
            *(uint4*)(pBl)     = pbl0;
            *(uint4*)(pBl + 4) = pbl1;
        }
        __syncthreads();

        // ---- prefetch next tile ----
        int ktn = kt + 32;
        if (ktn < K) {
            int kwn = ktn >> 1;
            pah0 = a_ok ? *(const uint4*)(Ahrow + kwn)     : z4;
            pah1 = a_ok ? *(const uint4*)(Ahrow + kwn + 4) : z4;
            pal0 = a_ok ? *(const uint4*)(Alrow + kwn)     : z4;
            pal1 = a_ok ? *(const uint4*)(Alrow + kwn + 4) : z4;
            pbh0 = *(const uint4*)(Bhrow + kwn);
            pbh1 = *(const uint4*)(Bhrow + kwn + 4);
            pbl0 = *(const uint4*)(Blrow + kwn);
            pbl1 = *(const uint4*)(Blrow + kwn + 4);
        }

        // ---- mma: 2 k-steps of 16 ----
#pragma unroll
        for (int kk = 0; kk < 2; kk++) {
            const int kb = kk * 8 + t;
            uint32_t bh[4][2], bl[4][2];
#pragma unroll
            for (int nt = 0; nt < 4; nt++) {
                int n = wn * 32 + nt * 8 + g;
                bh[nt][0] = Bh[n * 20 + kb];
                bh[nt][1] = Bh[n * 20 + kb + 4];
                bl[nt][0] = Bl[n * 20 + kb];
                bl[nt][1] = Bl[n * 20 + kb + 4];
            }
#pragma unroll
            for (int mt = 0; mt < 4; mt++) {
                int rb = wm * 64 + mt * 16 + g;
                uint32_t ah[4], al[4];
                ah[0] = Ah[rb * 20 + kb];
                ah[1] = Ah[(rb + 8) * 20 + kb];
                ah[2] = Ah[rb * 20 + kb + 4];
                ah[3] = Ah[(rb + 8) * 20 + kb + 4];
                al[0] = Al[rb * 20 + kb];
                al[1] = Al[(rb + 8) * 20 + kb];
                al[2] = Al[rb * 20 + kb + 4];
                al[3] = Al[(rb + 8) * 20 + kb + 4];
#pragma unroll
                for (int nt = 0; nt < 4; nt++) {
                    mma_bf16(acc[mt][nt], ah[0], ah[1], ah[2], ah[3], bh[nt][0], bh[nt][1]);
                    mma_bf16(acc[mt][nt], ah[0], ah[1], ah[2], ah[3], bl[nt][0], bl[nt][1]);
                    mma_bf16(acc[mt][nt], al[0], al[1], al[2], al[3], bh[nt][0], bh[nt][1]);
                }
            }
        }
        __syncthreads();
    }

    // ---- epilogue 1: store C tile ----
#pragma unroll
    for (int mt = 0; mt < 4; mt++) {
        int r0 = row0 + wm * 64 + mt * 16 + g;
        int r1 = r0 + 8;
#pragma unroll
        for (int nt = 0; nt < 4; nt++) {
            int col = col0 + wn * 32 + nt * 8 + 2 * t;
            if (r0 < M)
                *(float2*)(C + (size_t)r0 * NF + col) = make_float2(acc[mt][nt][0], acc[mt][nt][1]);
            if (r1 < M)
                *(float2*)(C + (size_t)r1 * NF + col) = make_float2(acc[mt][nt][2], acc[mt][nt][3]);
        }
    }

    // ---- epilogue 2: fused alpha projection (atomic accumulate; buffers are
    //      zeroed every call by hist_kernel) ----
    {
        float asv[4][2], adv[4][2];
#pragma unroll
        for (int nt = 0; nt < 4; nt++)
#pragma unroll
            for (int i = 0; i < 2; i++) {
                int gcol = col0 + wn * 32 + nt * 8 + 2 * t + i;
                asv[nt][i] = a_s[gcol];
                adv[nt][i] = a_d[gcol];
            }
        const int hd = (H == 4) ? ((col0 + wn * 32) >> 6) : 0;
#pragma unroll
        for (int mt = 0; mt < 4; mt++) {
            float sa0 = 0.f, sd0 = 0.f, sa1 = 0.f, sd1 = 0.f;
#pragma unroll
            for (int nt = 0; nt < 4; nt++)
#pragma unroll
                for (int i = 0; i < 2; i++) {
                    sa0 += acc[mt][nt][i]     * asv[nt][i];
                    sd0 += acc[mt][nt][i]     * adv[nt][i];
                    sa1 += acc[mt][nt][2 + i] * asv[nt][i];
                    sd1 += acc[mt][nt][2 + i] * adv[nt][i];
                }
#pragma unroll
            for (int o = 1; o <= 2; o <<= 1) {
                sa0 += __shfl_xor_sync(0xffffffffu, sa0, o);
                sd0 += __shfl_xor_sync(0xffffffffu, sd0, o);
                sa1 += __shfl_xor_sync(0xffffffffu, sa1, o);
                sd1 += __shfl_xor_sync(0xffffffffu, sd1, o);
            }
            if (t == 0) {
                int r0 = row0 + wm * 64 + mt * 16 + g;
                int r1 = r0 + 8;
                if (r0 < M) {
                    atomicAdd(&asrc[r0 * H + hd], sa0);
                    atomicAdd(&adst[r0 * H + hd], sd0);
                }
                if (r1 < M) {
                    atomicAdd(&asrc[r1 * H + hd], sa1);
                    atomicAdd(&adst[r1 * H + hd], sd1);
                }
            }
        }
    }
}

// ---------------- block-sum helper (64 threads, 2 warps) ---------------------
__device__ __forceinline__ float block_sum64(float v, float* red) {
#pragma unroll
    for (int o = 16; o > 0; o >>= 1) v += __shfl_xor_sync(0xffffffffu, v, o);
    int wid = threadIdx.x >> 5;
    if ((threadIdx.x & 31) == 0) red[wid] = v;
    __syncthreads();
    float s = red[0] + red[1];
    __syncthreads();
    return s;
}

// ---------------- fused aggregation + bias + LN + ELU -----------------------
// SPLIT=true: write bf16 hi/lo split (next layer's GEMM input).
// SPLIT=false: write fp32 (final output).
template <int H, bool SPLIT>
__global__ void __launch_bounds__(64) agg_kernel(
    const float4* __restrict__ hfeat4,
    const float* __restrict__ asrc, const float* __restrict__ adst,
    const int* __restrict__ rowptr, const int* __restrict__ colsrc,
    const float* __restrict__ wexp,
    const float4* __restrict__ bias4, const float4* __restrict__ lnw4,
    const float4* __restrict__ lnb4,
    float4* __restrict__ out4,
    uint32_t* __restrict__ yh, uint32_t* __restrict__ yl)
{
    __shared__ float red[2];

    int i   = blockIdx.x;
    int tid = threadIdx.x;
    int head = (H == 4) ? (tid >> 4) : 0;

    float e0 = asrc[i * H + head] + adst[i * H + head];
    e0 = e0 > 0.f ? e0 : 0.2f * e0;
    float w0 = __expf(e0);
    float den = w0;
    float4 hv = hfeat4[(size_t)i * 64 + tid];
    float4 acc = make_float4(w0 * hv.x, w0 * hv.y, w0 * hv.z, w0 * hv.w);

    int beg = rowptr[i], end = rowptr[i + 1];
    int p = beg;
    for (; p + 4 <= end; p += 4) {
        int s0 = colsrc[p], s1 = colsrc[p + 1], s2 = colsrc[p + 2], s3 = colsrc[p + 3];
        float w_0 = wexp[(p + 0) * H + head];
        float w_1 = wexp[(p + 1) * H + head];
        float w_2 = wexp[(p + 2) * H + head];
        float w_3 = wexp[(p + 3) * H + head];
        float4 h0 = hfeat4[(size_t)s0 * 64 + tid];
        float4 h1 = hfeat4[(size_t)s1 * 64 + tid];
        float4 h2 = hfeat4[(size_t)s2 * 64 + tid];
        float4 h3 = hfeat4[(size_t)s3 * 64 + tid];
        den += (w_0 + w_1) + (w_2 + w_3);
        acc.x += w_0 * h0.x + w_1 * h1.x + w_2 * h2.x + w_3 * h3.x;
        acc.y += w_0 * h0.y + w_1 * h1.y + w_2 * h2.y + w_3 * h3.y;
        acc.z += w_0 * h0.z + w_1 * h1.z + w_2 * h2.z + w_3 * h3.z;
        acc.w += w_0 * h0.w + w_1 * h1.w + w_2 * h2.w + w_3 * h3.w;
    }
    for (; p < end; p++) {
        int s0 = colsrc[p];
        float wv = wexp[p * H + head];
        float4 h0 = hfeat4[(size_t)s0 * 64 + tid];
        den += wv;
        acc.x += wv * h0.x; acc.y += wv * h0.y; acc.z += wv * h0.z; acc.w += wv * h0.w;
    }

    float4 bv = bias4[tid];
    float inv = 1.f / den;
    float4 v = make_float4(acc.x * inv + bv.x, acc.y * inv + bv.y,
                           acc.z * inv + bv.z, acc.w * inv + bv.w);

    float mean = block_sum64(v.x + v.y + v.z + v.w, red) * (1.f / NF);
    float4 dl = make_float4(v.x - mean, v.y - mean, v.z - mean, v.w - mean);
    float var = block_sum64(dl.x * dl.x + dl.y * dl.y + dl.z * dl.z + dl.w * dl.w, red)
                * (1.f / NF);
    float rs = rsqrtf(var + 1e-5f);
    float4 wv4 = lnw4[tid];
    float4 bb = lnb4[tid];
    float4 y;
    y.x = dl.x * rs * wv4.x + bb.x;
    y.y = dl.y * rs * wv4.y + bb.y;
    y.z = dl.z * rs * wv4.z + bb.z;
    y.w = dl.w * rs * wv4.w + bb.w;
    y.x = y.x > 0.f ? y.x : expm1f(y.x);
    y.y = y.y > 0.f ? y.y : expm1f(y.y);
    y.z = y.z > 0.f ? y.z : expm1f(y.z);
    y.w = y.w > 0.f ? y.w : expm1f(y.w);

    if (SPLIT) {
        uint2 hi, lo;
        hi.x = bf16_pack_hi(y.x, y.y);
        hi.y = bf16_pack_hi(y.z, y.w);
        lo.x = bf16_pack_lo(y.x, y.y);
        lo.y = bf16_pack_lo(y.z, y.w);
        *(uint2*)(yh + (size_t)i * 128 + 2 * tid) = hi;
        *(uint2*)(yl + (size_t)i * 128 + 2 * tid) = lo;
    } else {
        out4[(size_t)i * 64 + tid] = y;
    }
}

// ---------------- launch ----------------------------------------------------
extern "C" void kernel_launch(void* const* d_in, const int* in_sizes, int n_in,
                              void* d_out, int out_size) {
    const float* x    = (const float*)d_in[0];
    const int*   ei   = (const int*)d_in[1];
    const float* W0   = (const float*)d_in[2];
    const float* as0  = (const float*)d_in[3];
    const float* ad0  = (const float*)d_in[4];
    const float* b0   = (const float*)d_in[5];
    const float* lnw0 = (const float*)d_in[6];
    const float* lnb0 = (const float*)d_in[7];
    const float* W1   = (const float*)d_in[8];
    const float* as1  = (const float*)d_in[9];
    const float* ad1  = (const float*)d_in[10];
    const float* b1   = (const float*)d_in[11];
    const float* lnw1 = (const float*)d_in[12];
    const float* lnb1 = (const float*)d_in[13];
    const float* W2   = (const float*)d_in[14];
    const float* as2  = (const float*)d_in[15];
    const float* ad2  = (const float*)d_in[16];
    const float* b2   = (const float*)d_in[17];
    const float* lnw2 = (const float*)d_in[18];
    const float* lnb2 = (const float*)d_in[19];
    float* out = (float*)d_out;

    int n = in_sizes[0] / 512;   // 50000
    int e = in_sizes[1] / 2;     // 800000
    const int* src = ei;
    const int* dst = ei + e;

    float *ph, *palpha, *pwexp;
    int *pcnt, *prow, *pcur, *pcol, *pcds;
    uint32_t *pxh, *pxl, *pyh, *pyl;
    uint32_t *pw0h, *pw0l, *pw1h, *pw1l, *pw2h, *pw2l;
    cudaGetSymbolAddress((void**)&ph, g_h);
    cudaGetSymbolAddress((void**)&palpha, g_alpha);
    cudaGetSymbolAddress((void**)&pwexp, g_wexp);
    cudaGetSymbolAddress((void**)&pcnt, g_cnt);
    cudaGetSymbolAddress((void**)&prow, g_rowptr);
    cudaGetSymbolAddress((void**)&pcur, g_cursor);
    cudaGetSymbolAddress((void**)&pcol, g_colsrc);
    cudaGetSymbolAddress((void**)&pcds, g_coldst);
    cudaGetSymbolAddress((void**)&pxh, g_xh);
    cudaGetSymbolAddress((void**)&pxl, g_xl);
    cudaGetSymbolAddress((void**)&pyh, g_yh);
    cudaGetSymbolAddress((void**)&pyl, g_yl);
    cudaGetSymbolAddress((void**)&pw0h, g_w0h);
    cudaGetSymbolAddress((void**)&pw0l, g_w0l);
    cudaGetSymbolAddress((void**)&pw1h, g_w1h);
    cudaGetSymbolAddress((void**)&pw1l, g_w1l);
    cudaGetSymbolAddress((void**)&pw2h, g_w2h);
    cudaGetSymbolAddress((void**)&pw2l, g_w2l);

    float* pas0 = palpha + (size_t)0 * MAXN * 4;
    float* pad0 = palpha + (size_t)1 * MAXN * 4;
    float* pas1 = palpha + (size_t)2 * MAXN * 4;
    float* pad1 = palpha + (size_t)3 * MAXN * 4;
    float* pas2 = palpha + (size_t)4 * MAXN * 4;
    float* pad2 = palpha + (size_t)5 * MAXN * 4;

    const int TPB = 256;
    const int egrid = (e + TPB - 1) / TPB;
    const int xtotal = n * 256;

    prep_x_kernel<<<(xtotal + TPB - 1) / TPB, TPB>>>((const float2*)x, pxh, pxl, xtotal);
    hist_kernel<<<egrid, TPB>>>(dst, pcnt, e, palpha, W0, W1, W2,
                                pw0h, pw0l, pw1h, pw1l, pw2h, pw2l);
    scan_kernel<<<1, 1024>>>(pcnt, prow, pcur, n);
    scatter_kernel<<<egrid, TPB>>>(src, dst, pcur, pcol, pcds, e);

    dim3 ggrid(NF / 128, (n + 127) / 128);

    // layer 0: GATConv(512 -> 4x64)
    gemm_bf16<4><<<ggrid, 256>>>(pxh, pxl, pw0h, pw0l, ph, n, 512, as0, ad0, pas0, pad0);
    weight_kernel<4><<<egrid, TPB>>>(pas0, pad0, pcol, pcds, pwexp, e);
    agg_kernel<4, true><<<n, 64>>>((const float4*)ph, pas0, pad0, prow, pcol, pwexp,
                                   (const float4*)b0, (const float4*)lnw0,
                                   (const float4*)lnb0, nullptr, pyh, pyl);

    // layer 1: GATConv(256 -> 4x64)
    gemm_bf16<4><<<ggrid, 256>>>(pyh, pyl, pw1h, pw1l, ph, n, 256, as1, ad1, pas1, pad1);
    weight_kernel<4><<<egrid, TPB>>>(pas1, pad1, pcol, pcds, pwexp, e);
    agg_kernel<4, true><<<n, 64>>>((const float4*)ph, pas1, pad1, prow, pcol, pwexp,
                                   (const float4*)b1, (const float4*)lnw1,
                                   (const float4*)lnb1, nullptr, pyh, pyl);

    // layer 2: GATConv(256 -> 1x256)
    gemm_bf16<1><<<ggrid, 256>>>(pyh, pyl, pw2h, pw2l, ph, n, 256, as2, ad2, pas2, pad2);
    weight_kernel<1><<<egrid, TPB>>>(pas2, pad2, pcol, pcds, pwexp, e);
    agg_kernel<1, false><<<n, 64>>>((const float4*)ph, pas2, pad2, prow, pcol, pwexp,
                                    (const float4*)b2, (const float4*)lnw2,
                                    (const float4*)lnb2, (float4*)out, nullptr, nullptr);
}

// round 12
// speedup vs baseline: 1.0743x; 1.0743x over previous
#include <cuda_runtime.h>
#include <cuda_bf16.h>
#include <stdint.h>
#include <math.h>

#define MAXN 50000
#define MAXE 800000
#define NF 256

// ---------------- scratch (device globals; no allocation allowed) ----------
__device__ float g_h[(size_t)MAXN * NF];     // GEMM fp32 output (for agg gather)
__device__ float g_buf[(size_t)MAXN * NF];   // layer output = next layer input
__device__ float g_alpha[(size_t)6 * MAXN * 4];
__device__ float g_wexp[(size_t)MAXE * 4];   // per-edge softmax numerators (CSR order)
__device__ int   g_cnt[MAXN];
__device__ int   g_rowptr[MAXN + 1];
__device__ int   g_cursor[MAXN];
__device__ int   g_colsrc[MAXE];
__device__ int   g_coldst[MAXE];
// pre-transposed, bf16-split weights: [n][kpair] packed bf16x2
__device__ uint32_t g_w0h[256 * 256], g_w0l[256 * 256];
__device__ uint32_t g_w1h[256 * 128], g_w1l[256 * 128];
__device__ uint32_t g_w2h[256 * 128], g_w2l[256 * 128];

// ---------------- bf16 split helpers ----------------------------------------
__device__ __forceinline__ uint32_t bf16_pack_hi(float f0, float f1) {
    __nv_bfloat16 h0 = __float2bfloat16(f0);
    __nv_bfloat16 h1 = __float2bfloat16(f1);
    return (uint32_t)__bfloat16_as_ushort(h0) | ((uint32_t)__bfloat16_as_ushort(h1) << 16);
}
__device__ __forceinline__ uint32_t bf16_pack_lo(float f0, float f1) {
    __nv_bfloat16 h0 = __float2bfloat16(f0);
    __nv_bfloat16 h1 = __float2bfloat16(f1);
    __nv_bfloat16 l0 = __float2bfloat16(f0 - __bfloat162float(h0));
    __nv_bfloat16 l1 = __float2bfloat16(f1 - __bfloat162float(h1));
    return (uint32_t)__bfloat16_as_ushort(l0) | ((uint32_t)__bfloat16_as_ushort(l1) << 16);
}

__device__ __forceinline__ void mma_bf16(float c[4],
                                         uint32_t a0, uint32_t a1, uint32_t a2, uint32_t a3,
                                         uint32_t b0, uint32_t b1) {
    asm volatile(
        "mma.sync.aligned.m16n8k16.row.col.f32.bf16.bf16.f32 "
        "{%0,%1,%2,%3}, {%4,%5,%6,%7}, {%8,%9}, {%0,%1,%2,%3};"
        : "+f"(c[0]), "+f"(c[1]), "+f"(c[2]), "+f"(c[3])
        : "r"(a0), "r"(a1), "r"(a2), "r"(a3), "r"(b0), "r"(b1));
}

// ---------------- hist + weight prep + alpha zero (fused) --------------------
__global__ void hist_kernel(const int* __restrict__ dst, int* __restrict__ cnt, int e,
                            float* __restrict__ alpha,
                            const float* __restrict__ W0, const float* __restrict__ W1,
                            const float* __restrict__ W2,
                            uint32_t* __restrict__ w0h, uint32_t* __restrict__ w0l,
                            uint32_t* __restrict__ w1h, uint32_t* __restrict__ w1l,
                            uint32_t* __restrict__ w2h, uint32_t* __restrict__ w2l) {
    int t = blockIdx.x * blockDim.x + threadIdx.x;
    if (t < e) atomicAdd(&cnt[dst[t]], 1);
    // zero alpha accumulators (GEMM epilogue accumulates atomically;
    // REQUIRED for graph-replay determinism)
    const int atot = 6 * MAXN * 4;
    for (int i = t; i < atot; i += gridDim.x * blockDim.x) alpha[i] = 0.f;
    const int T0 = 256 * 256, T1 = 256 * 128;
    if (t < T0) {
        int n = t >> 8, kp = t & 255;
        float f0 = W0[(2 * kp) * 256 + n];
        float f1 = W0[(2 * kp + 1) * 256 + n];
        w0h[n * 256 + kp] = bf16_pack_hi(f0, f1);
        w0l[n * 256 + kp] = bf16_pack_lo(f0, f1);
    } else if (t < T0 + T1) {
        int id = t - T0;
        int n = id >> 7, kp = id & 127;
        float f0 = W1[(2 * kp) * 256 + n];
        float f1 = W1[(2 * kp + 1) * 256 + n];
        w1h[n * 128 + kp] = bf16_pack_hi(f0, f1);
        w1l[n * 128 + kp] = bf16_pack_lo(f0, f1);
    } else if (t < T0 + 2 * T1) {
        int id = t - T0 - T1;
        int n = id >> 7, kp = id & 127;
        float f0 = W2[(2 * kp) * 256 + n];
        float f1 = W2[(2 * kp + 1) * 256 + n];
        w2h[n * 128 + kp] = bf16_pack_hi(f0, f1);
        w2l[n * 128 + kp] = bf16_pack_lo(f0, f1);
    }
}

__global__ void scan_kernel(int* __restrict__ cnt, int* __restrict__ rowptr,
                            int* __restrict__ cursor, int n) {
    __shared__ int sh[1024];
    int tid = threadIdx.x;
    int chunk = (n + 1023) >> 10;
    int base = tid * chunk;
    int s = 0;
    for (int j = 0; j < chunk; j++) {
        int idx = base + j;
        if (idx < n) s += cnt[idx];
    }
    sh[tid] = s;
    __syncthreads();
    for (int off = 1; off < 1024; off <<= 1) {
        int v = (tid >= off) ? sh[tid - off] : 0;
        __syncthreads();
        sh[tid] += v;
        __syncthreads();
    }
    int run = sh[tid] - s;
    for (int j = 0; j < chunk; j++) {
        int idx = base + j;
        if (idx < n) {
            rowptr[idx] = run;
            cursor[idx] = run;
            run += cnt[idx];
            cnt[idx] = 0;
        }
    }
    if (tid == 1023) rowptr[n] = run;
}

__global__ void scatter_kernel(const int* __restrict__ src, const int* __restrict__ dst,
                               int* __restrict__ cursor, int* __restrict__ colsrc,
                               int* __restrict__ coldst, int e) {
    int t = blockIdx.x * blockDim.x + threadIdx.x;
    if (t < e) {
        int d = dst[t];
        int p = atomicAdd(&cursor[d], 1);
        colsrc[p] = src[t];
        coldst[p] = d;
    }
}

// ---------------- per-edge softmax numerators --------------------------------
template <int H>
__global__ void weight_kernel(const float* __restrict__ asrc, const float* __restrict__ adst,
                              const int* __restrict__ colsrc, const int* __restrict__ coldst,
                              float* __restrict__ wexp, int e) {
    int t = blockIdx.x * blockDim.x + threadIdx.x;
    if (t < e) {
        int s = colsrc[t], d = coldst[t];
#pragma unroll
        for (int h = 0; h < H; h++) {
            float ev = asrc[s * H + h] + adst[d * H + h];
            ev = ev > 0.f ? ev : 0.2f * ev;
            wexp[t * H + h] = __expf(ev);
        }
    }
}

// ---------------- bf16x3 tensor-core GEMM + fused alpha projection ----------
// C[M,256] = A[M,K] @ B[K,256]; A fp32 (split in-loop), B pre-split [n][kpair].
// 128x128 CTA tile, BK=32, 8 warps (2x4), warp tile 64x32, m16n8k16 bf16 mma,
// 3-term split. MMA issue is TERM-MAJOR per mt-row so dependent mmas on the
// same accumulator are 4 independent issues apart (hides HMMA latency).
template <int H>
__global__ void __launch_bounds__(256, 2) gemm_bf16(
    const float* __restrict__ A,
    const uint32_t* __restrict__ Bth, const uint32_t* __restrict__ Btl,
    float* __restrict__ C, int M, int K,
    const float* __restrict__ a_s, const float* __restrict__ a_d,
    float* __restrict__ asrc, float* __restrict__ adst)
{
    __shared__ uint32_t Ah[128 * 20];
    __shared__ uint32_t Al[128 * 20];
    __shared__ uint32_t Bh[128 * 20];
    __shared__ uint32_t Bl[128 * 20];

    const int tid  = threadIdx.x;
    const int lane = tid & 31;
    const int w    = tid >> 5;
    const int g    = lane >> 2;
    const int t    = lane & 3;
    const int wm   = w >> 2;
    const int wn   = w & 3;

    const int row0 = blockIdx.y * 128;
    const int col0 = blockIdx.x * 128;
    const int KW   = K >> 1;

    // staging indices
    const int ar  = tid >> 1;             // row 0..127
    const int ak16 = (tid & 1) << 4;      // A k base within tile: 0 or 16
    const int bk8 = (tid & 1) << 3;       // B kpair base: 0 or 8
    const bool a_ok = (row0 + ar) < M;

    const float*    Arow  = A + (size_t)(row0 + ar) * K + ak16;
    const uint32_t* Bhrow = Bth + (size_t)(col0 + ar) * KW + bk8;
    const uint32_t* Blrow = Btl + (size_t)(col0 + ar) * KW + bk8;

    float acc[4][4][4];
#pragma unroll
    for (int mt = 0; mt < 4; mt++)
#pragma unroll
        for (int nt = 0; nt < 4; nt++)
#pragma unroll
            for (int i = 0; i < 4; i++) acc[mt][nt][i] = 0.f;

    const float4 zf = make_float4(0.f, 0.f, 0.f, 0.f);
    float4 pa[4];
    uint4  pbh0, pbh1, pbl0, pbl1;

    // prefetch tile 0
#pragma unroll
    for (int i = 0; i < 4; i++)
        pa[i] = a_ok ? *(const float4*)(Arow + i * 4) : zf;
    pbh0 = *(const uint4*)(Bhrow);
    pbh1 = *(const uint4*)(Bhrow + 4);
    pbl0 = *(const uint4*)(Blrow);
    pbl1 = *(const uint4*)(Blrow + 4);

    for (int kt = 0; kt < K; kt += 32) {
        // ---- convert/store staged tile ----
        {
            uint32_t wh[8], wl[8];
#pragma unroll
            for (int i = 0; i < 4; i++) {
                wh[2 * i]     = bf16_pack_hi(pa[i].x, pa[i].y);
                wh[2 * i + 1] = bf16_pack_hi(pa[i].z, pa[i].w);
                wl[2 * i]     = bf16_pack_lo(pa[i].x, pa[i].y);
                wl[2 * i + 1] = bf16_pack_lo(pa[i].z, pa[i].w);
            }
            uint32_t* pA  = &Ah[ar * 20 + (ak16 >> 1)];
            uint32_t* pAl = &Al[ar * 20 + (ak16 >> 1)];
            *(uint4*)(pA)      = make_uint4(wh[0], wh[1], wh[2], wh[3]);
            *(uint4*)(pA + 4)  = make_uint4(wh[4], wh[5], wh[6], wh[7]);
            *(uint4*)(pAl)     = make_uint4(wl[0], wl[1], wl[2], wl[3]);
            *(uint4*)(pAl + 4) = make_uint4(wl[4], wl[5], wl[6], wl[7]);
            uint32_t* pB  = &Bh[ar * 20 + bk8];
            uint32_t* pBl = &Bl[ar * 20 + bk8];
            *(uint4*)(pB)      = pbh0;
            *(uint4*)(pB + 4)  = pbh1;
            *(uint4*)(pBl)     = pbl0;
            *(uint4*)(pBl + 4) = pbl1;
        }
        __syncthreads();

        // ---- prefetch next tile ----
        int ktn = kt + 32;
        if (ktn < K) {
#pragma unroll
            for (int i = 0; i < 4; i++)
                pa[i] = a_ok ? *(const float4*)(Arow + ktn + i * 4) : zf;
            int kwn = ktn >> 1;
            pbh0 = *(const uint4*)(Bhrow + kwn);
            pbh1 = *(const uint4*)(Bhrow + kwn + 4);
            pbl0 = *(const uint4*)(Blrow + kwn);
            pbl1 = *(const uint4*)(Blrow + kwn + 4);
        }

        // ---- mma: 2 k-steps of 16; term-major per mt (dependency dist = 4) --
#pragma unroll
        for (int kk = 0; kk < 2; kk++) {
            const int kb = kk * 8 + t;
            uint32_t bh[4][2], bl[4][2];
#pragma unroll
            for (int nt = 0; nt < 4; nt++) {
                int n = wn * 32 + nt * 8 + g;
                bh[nt][0] = Bh[n * 20 + kb];
                bh[nt][1] = Bh[n * 20 + kb + 4];
                bl[nt][0] = Bl[n * 20 + kb];
                bl[nt][1] = Bl[n * 20 + kb + 4];
            }
#pragma unroll
            for (int mt = 0; mt < 4; mt++) {
                int rb = wm * 64 + mt * 16 + g;
                uint32_t ah[4], al[4];
                ah[0] = Ah[rb * 20 + kb];
                ah[1] = Ah[(rb + 8) * 20 + kb];
                ah[2] = Ah[rb * 20 + kb + 4];
                ah[3] = Ah[(rb + 8) * 20 + kb + 4];
                al[0] = Al[rb * 20 + kb];
                al[1] = Al[(rb + 8) * 20 + kb];
                al[2] = Al[rb * 20 + kb + 4];
                al[3] = Al[(rb + 8) * 20 + kb + 4];
                // term HH across all nt
#pragma unroll
                for (int nt = 0; nt < 4; nt++)
                    mma_bf16(acc[mt][nt], ah[0], ah[1], ah[2], ah[3], bh[nt][0], bh[nt][1]);
                // term HL across all nt
#pragma unroll
                for (int nt = 0; nt < 4; nt++)
                    mma_bf16(acc[mt][nt], ah[0], ah[1], ah[2], ah[3], bl[nt][0], bl[nt][1]);
                // term LH across all nt
#pragma unroll
                for (int nt = 0; nt < 4; nt++)
                    mma_bf16(acc[mt][nt], al[0], al[1], al[2], al[3], bh[nt][0], bh[nt][1]);
            }
        }
        __syncthreads();
    }

    // ---- epilogue 1: store C tile ----
#pragma unroll
    for (int mt = 0; mt < 4; mt++) {
        int r0 = row0 + wm * 64 + mt * 16 + g;
        int r1 = r0 + 8;
#pragma unroll
        for (int nt = 0; nt < 4; nt++) {
            int col = col0 + wn * 32 + nt * 8 + 2 * t;
            if (r0 < M)
                *(float2*)(C + (size_t)r0 * NF + col) = make_float2(acc[mt][nt][0], acc[mt][nt][1]);
            if (r1 < M)
                *(float2*)(C + (size_t)r1 * NF + col) = make_float2(acc[mt][nt][2], acc[mt][nt][3]);
        }
    }

    // ---- epilogue 2: fused alpha projection (atomic; zeroed by hist) -------
    {
        float asv[4][2], adv[4][2];
#pragma unroll
        for (int nt = 0; nt < 4; nt++)
#pragma unroll
            for (int i = 0; i < 2; i++) {
                int gcol = col0 + wn * 32 + nt * 8 + 2 * t + i;
                asv[nt][i] = a_s[gcol];
                adv[nt][i] = a_d[gcol];
            }
        const int hd = (H == 4) ? ((col0 + wn * 32) >> 6) : 0;
#pragma unroll
        for (int mt = 0; mt < 4; mt++) {
            float sa0 = 0.f, sd0 = 0.f, sa1 = 0.f, sd1 = 0.f;
#pragma unroll
            for (int nt = 0; nt < 4; nt++)
#pragma unroll
                for (int i = 0; i < 2; i++) {
                    sa0 += acc[mt][nt][i]     * asv[nt][i];
                    sd0 += acc[mt][nt][i]     * adv[nt][i];
                    sa1 += acc[mt][nt][2 + i] * asv[nt][i];
                    sd1 += acc[mt][nt][2 + i] * adv[nt][i];
                }
#pragma unroll
            for (int o = 1; o <= 2; o <<= 1) {
                sa0 += __shfl_xor_sync(0xffffffffu, sa0, o);
                sd0 += __shfl_xor_sync(0xffffffffu, sd0, o);
                sa1 += __shfl_xor_sync(0xffffffffu, sa1, o);
                sd1 += __shfl_xor_sync(0xffffffffu, sd1, o);
            }
            if (t == 0) {
                int r0 = row0 + wm * 64 + mt * 16 + g;
                int r1 = r0 + 8;
                if (r0 < M) {
                    atomicAdd(&asrc[r0 * H + hd], sa0);
                    atomicAdd(&adst[r0 * H + hd], sd0);
                }
                if (r1 < M) {
                    atomicAdd(&asrc[r1 * H + hd], sa1);
                    atomicAdd(&adst[r1 * H + hd], sd1);
                }
            }
        }
    }
}

// ---------------- block-sum helper (64 threads, 2 warps) ---------------------
__device__ __forceinline__ float block_sum64(float v, float* red) {
#pragma unroll
    for (int o = 16; o > 0; o >>= 1) v += __shfl_xor_sync(0xffffffffu, v, o);
    int wid = threadIdx.x >> 5;
    if ((threadIdx.x & 31) == 0) red[wid] = v;
    __syncthreads();
    float s = red[0] + red[1];
    __syncthreads();
    return s;
}

// ---------------- fused aggregation + bias + LN + ELU -----------------------
template <int H>
__global__ void __launch_bounds__(64) agg_kernel(
    const float4* __restrict__ hfeat4,
    const float* __restrict__ asrc, const float* __restrict__ adst,
    const int* __restrict__ rowptr, const int* __restrict__ colsrc,
    const float* __restrict__ wexp,
    const float4* __restrict__ bias4, const float4* __restrict__ lnw4,
    const float4* __restrict__ lnb4, float4* __restrict__ out4)
{
    __shared__ float red[2];

    int i   = blockIdx.x;
    int tid = threadIdx.x;
    int head = (H == 4) ? (tid >> 4) : 0;

    float e0 = asrc[i * H + head] + adst[i * H + head];
    e0 = e0 > 0.f ? e0 : 0.2f * e0;
    float w0 = __expf(e0);
    float den = w0;
    float4 hv = hfeat4[(size_t)i * 64 + tid];
    float4 acc = make_float4(w0 * hv.x, w0 * hv.y, w0 * hv.z, w0 * hv.w);

    int beg = rowptr[i], end = rowptr[i + 1];
    int p = beg;
    for (; p + 4 <= end; p += 4) {
        int s0 = colsrc[p], s1 = colsrc[p + 1], s2 = colsrc[p + 2], s3 = colsrc[p + 3];
        float w_0 = wexp[(p + 0) * H + head];
        float w_1 = wexp[(p + 1) * H + head];
        float w_2 = wexp[(p + 2) * H + head];
        float w_3 = wexp[(p + 3) * H + head];
        float4 h0 = hfeat4[(size_t)s0 * 64 + tid];
        float4 h1 = hfeat4[(size_t)s1 * 64 + tid];
        float4 h2 = hfeat4[(size_t)s2 * 64 + tid];
        float4 h3 = hfeat4[(size_t)s3 * 64 + tid];
        den += (w_0 + w_1) + (w_2 + w_3);
        acc.x += w_0 * h0.x + w_1 * h1.x + w_2 * h2.x + w_3 * h3.x;
        acc.y += w_0 * h0.y + w_1 * h1.y + w_2 * h2.y + w_3 * h3.y;
        acc.z += w_0 * h0.z + w_1 * h1.z + w_2 * h2.z + w_3 * h3.z;
        acc.w += w_0 * h0.w + w_1 * h1.w + w_2 * h2.w + w_3 * h3.w;
    }
    for (; p < end; p++) {
        int s0 = colsrc[p];
        float wv = wexp[p * H + head];
        float4 h0 = hfeat4[(size_t)s0 * 64 + tid];
        den += wv;
        acc.x += wv * h0.x; acc.y += wv * h0.y; acc.z += wv * h0.z; acc.w += wv * h0.w;
    }

    float4 bv = bias4[tid];
    float inv = 1.f / den;
    float4 v = make_float4(acc.x * inv + bv.x, acc.y * inv + bv.y,
                           acc.z * inv + bv.z, acc.w * inv + bv.w);

    float mean = block_sum64(v.x + v.y + v.z + v.w, red) * (1.f / NF);
    float4 dl = make_float4(v.x - mean, v.y - mean, v.z - mean, v.w - mean);
    float var = block_sum64(dl.x * dl.x + dl.y * dl.y + dl.z * dl.z + dl.w * dl.w, red)
                * (1.f / NF);
    float rs = rsqrtf(var + 1e-5f);
    float4 wv4 = lnw4[tid];
    float4 bb = lnb4[tid];
    float4 y;
    y.x = dl.x * rs * wv4.x + bb.x;
    y.y = dl.y * rs * wv4.y + bb.y;
    y.z = dl.z * rs * wv4.z + bb.z;
    y.w = dl.w * rs * wv4.w + bb.w;
    y.x = y.x > 0.f ? y.x : expm1f(y.x);
    y.y = y.y > 0.f ? y.y : expm1f(y.y);
    y.z = y.z > 0.f ? y.z : expm1f(y.z);
    y.w = y.w > 0.f ? y.w : expm1f(y.w);
    out4[(size_t)i * 64 + tid] = y;
}

// ---------------- launch ----------------------------------------------------
extern "C" void kernel_launch(void* const* d_in, const int* in_sizes, int n_in,
                              void* d_out, int out_size) {
    const float* x    = (const float*)d_in[0];
    const int*   ei   = (const int*)d_in[1];
    const float* W0   = (const float*)d_in[2];
    const float* as0  = (const float*)d_in[3];
    const float* ad0  = (const float*)d_in[4];
    const float* b0   = (const float*)d_in[5];
    const float* lnw0 = (const float*)d_in[6];
    const float* lnb0 = (const float*)d_in[7];
    const float* W1   = (const float*)d_in[8];
    const float* as1  = (const float*)d_in[9];
    const float* ad1  = (const float*)d_in[10];
    const float* b1   = (const float*)d_in[11];
    const float* lnw1 = (const float*)d_in[12];
    const float* lnb1 = (const float*)d_in[13];
    const float* W2   = (const float*)d_in[14];
    const float* as2  = (const float*)d_in[15];
    const float* ad2  = (const float*)d_in[16];
    const float* b2   = (const float*)d_in[17];
    const float* lnw2 = (const float*)d_in[18];
    const float* lnb2 = (const float*)d_in[19];
    float* out = (float*)d_out;

    int n = in_sizes[0] / 512;   // 50000
    int e = in_sizes[1] / 2;     // 800000
    const int* src = ei;
    const int* dst = ei + e;

    float *ph, *pbuf, *palpha, *pwexp;
    int *pcnt, *prow, *pcur, *pcol, *pcds;
    uint32_t *pw0h, *pw0l, *pw1h, *pw1l, *pw2h, *pw2l;
    cudaGetSymbolAddress((void**)&ph, g_h);
    cudaGetSymbolAddress((void**)&pbuf, g_buf);
    cudaGetSymbolAddress((void**)&palpha, g_alpha);
    cudaGetSymbolAddress((void**)&pwexp, g_wexp);
    cudaGetSymbolAddress((void**)&pcnt, g_cnt);
    cudaGetSymbolAddress((void**)&prow, g_rowptr);
    cudaGetSymbolAddress((void**)&pcur, g_cursor);
    cudaGetSymbolAddress((void**)&pcol, g_colsrc);
    cudaGetSymbolAddress((void**)&pcds, g_coldst);
    cudaGetSymbolAddress((void**)&pw0h, g_w0h);
    cudaGetSymbolAddress((void**)&pw0l, g_w0l);
    cudaGetSymbolAddress((void**)&pw1h, g_w1h);
    cudaGetSymbolAddress((void**)&pw1l, g_w1l);
    cudaGetSymbolAddress((void**)&pw2h, g_w2h);
    cudaGetSymbolAddress((void**)&pw2l, g_w2l);

    float* pas0 = palpha + (size_t)0 * MAXN * 4;
    float* pad0 = palpha + (size_t)1 * MAXN * 4;
    float* pas1 = palpha + (size_t)2 * MAXN * 4;
    float* pad1 = palpha + (size_t)3 * MAXN * 4;
    float* pas2 = palpha + (size_t)4 * MAXN * 4;
    float* pad2 = palpha + (size_t)5 * MAXN * 4;

    const int TPB = 256;
    const int egrid = (e + TPB - 1) / TPB;
    hist_kernel<<<egrid, TPB>>>(dst, pcnt, e, palpha, W0, W1, W2,
                                pw0h, pw0l, pw1h, pw1l, pw2h, pw2l);
    scan_kernel<<<1, 1024>>>(pcnt, prow, pcur, n);
    scatter_kernel<<<egrid, TPB>>>(src, dst, pcur, pcol, pcds, e);

    dim3 ggrid(NF / 128, (n + 127) / 128);

    // layer 0: GATConv(512 -> 4x64)
    gemm_bf16<4><<<ggrid, 256>>>(x, pw0h, pw0l, ph, n, 512, as0, ad0, pas0, pad0);
    weight_kernel<4><<<egrid, TPB>>>(pas0, pad0, pcol, pcds, pwexp, e);
    agg_kernel<4><<<n, 64>>>((const float4*)ph, pas0, pad0, prow, pcol, pwexp,
                             (const float4*)b0, (const float4*)lnw0,
                             (const float4*)lnb0, (float4*)pbuf);

    // layer 1: GATConv(256 -> 4x64)
    gemm_bf16<4><<<ggrid, 256>>>(pbuf, pw1h, pw1l, ph, n, 256, as1, ad1, pas1, pad1);
    weight_kernel<4><<<egrid, TPB>>>(pas1, pad1, pcol, pcds, pwexp, e);
    agg_kernel<4><<<n, 64>>>((const float4*)ph, pas1, pad1, prow, pcol, pwexp,
                             (const float4*)b1, (const float4*)lnw1,
                             (const float4*)lnb1, (float4*)pbuf);

    // layer 2: GATConv(256 -> 1x256)
    gemm_bf16<1><<<ggrid, 256>>>(pbuf, pw2h, pw2l, ph, n, 256, as2, ad2, pas2, pad2);
    weight_kernel<1><<<egrid, TPB>>>(pas2, pad2, pcol, pcds, pwexp, e);
    agg_kernel<1><<<n, 64>>>((const float4*)ph, pas2, pad2, prow, pcol, pwexp,
                             (const float4*)b2, (const float4*)lnw2,
                             (const float4*)lnb2, (float4*)out);
}

// round 13
// speedup vs baseline: 1.0922x; 1.0166x over previous
#include <cuda_runtime.h>
#include <cuda_bf16.h>
#include <stdint.h>
#include <math.h>

#define MAXN 50000
#define MAXE 800000
#define NF 256

// ---------------- scratch (device globals; no allocation allowed) ----------
__device__ float g_h[(size_t)MAXN * NF];     // GEMM fp32 output (for agg gather)
__device__ float g_buf[(size_t)MAXN * NF];   // layer output = next layer input
__device__ float g_alpha[(size_t)6 * MAXN * 4];
__device__ float g_wexp[(size_t)MAXE * 4];   // per-edge softmax numerators (CSR order)
__device__ int   g_cnt[MAXN];
__device__ int   g_rowptr[MAXN + 1];
__device__ int   g_cursor[MAXN];
__device__ int   g_colsrc[MAXE];
__device__ int   g_coldst[MAXE];
// pre-transposed, bf16-split weights: [n][kpair] packed bf16x2
__device__ uint32_t g_w0h[256 * 256], g_w0l[256 * 256];
__device__ uint32_t g_w1h[256 * 128], g_w1l[256 * 128];
__device__ uint32_t g_w2h[256 * 128], g_w2l[256 * 128];

// ---------------- bf16 split helpers ----------------------------------------
__device__ __forceinline__ uint32_t bf16_pack_hi(float f0, float f1) {
    __nv_bfloat16 h0 = __float2bfloat16(f0);
    __nv_bfloat16 h1 = __float2bfloat16(f1);
    return (uint32_t)__bfloat16_as_ushort(h0) | ((uint32_t)__bfloat16_as_ushort(h1) << 16);
}
__device__ __forceinline__ uint32_t bf16_pack_lo(float f0, float f1) {
    __nv_bfloat16 h0 = __float2bfloat16(f0);
    __nv_bfloat16 h1 = __float2bfloat16(f1);
    __nv_bfloat16 l0 = __float2bfloat16(f0 - __bfloat162float(h0));
    __nv_bfloat16 l1 = __float2bfloat16(f1 - __bfloat162float(h1));
    return (uint32_t)__bfloat16_as_ushort(l0) | ((uint32_t)__bfloat16_as_ushort(l1) << 16);
}

__device__ __forceinline__ void mma_bf16(float c[4],
                                         uint32_t a0, uint32_t a1, uint32_t a2, uint32_t a3,
                                         uint32_t b0, uint32_t b1) {
    asm volatile(
        "mma.sync.aligned.m16n8k16.row.col.f32.bf16.bf16.f32 "
        "{%0,%1,%2,%3}, {%4,%5,%6,%7}, {%8,%9}, {%0,%1,%2,%3};"
        : "+f"(c[0]), "+f"(c[1]), "+f"(c[2]), "+f"(c[3])
        : "r"(a0), "r"(a1), "r"(a2), "r"(a3), "r"(b0), "r"(b1));
}

// ---------------- hist + weight prep + alpha zero (fused) --------------------
__global__ void hist_kernel(const int* __restrict__ dst, int* __restrict__ cnt, int e,
                            float* __restrict__ alpha,
                            const float* __restrict__ W0, const float* __restrict__ W1,
                            const float* __restrict__ W2,
                            uint32_t* __restrict__ w0h, uint32_t* __restrict__ w0l,
                            uint32_t* __restrict__ w1h, uint32_t* __restrict__ w1l,
                            uint32_t* __restrict__ w2h, uint32_t* __restrict__ w2l) {
    int t = blockIdx.x * blockDim.x + threadIdx.x;
    if (t < e) atomicAdd(&cnt[dst[t]], 1);
    // zero alpha accumulators (GEMM epilogue accumulates atomically;
    // REQUIRED for graph-replay determinism)
    const int atot = 6 * MAXN * 4;
    for (int i = t; i < atot; i += gridDim.x * blockDim.x) alpha[i] = 0.f;
    const int T0 = 256 * 256, T1 = 256 * 128;
    if (t < T0) {
        int n = t >> 8, kp = t & 255;
        float f0 = W0[(2 * kp) * 256 + n];
        float f1 = W0[(2 * kp + 1) * 256 + n];
        w0h[n * 256 + kp] = bf16_pack_hi(f0, f1);
        w0l[n * 256 + kp] = bf16_pack_lo(f0, f1);
    } else if (t < T0 + T1) {
        int id = t - T0;
        int n = id >> 7, kp = id & 127;
        float f0 = W1[(2 * kp) * 256 + n];
        float f1 = W1[(2 * kp + 1) * 256 + n];
        w1h[n * 128 + kp] = bf16_pack_hi(f0, f1);
        w1l[n * 128 + kp] = bf16_pack_lo(f0, f1);
    } else if (t < T0 + 2 * T1) {
        int id = t - T0 - T1;
        int n = id >> 7, kp = id & 127;
        float f0 = W2[(2 * kp) * 256 + n];
        float f1 = W2[(2 * kp + 1) * 256 + n];
        w2h[n * 128 + kp] = bf16_pack_hi(f0, f1);
        w2l[n * 128 + kp] = bf16_pack_lo(f0, f1);
    }
}

__global__ void scan_kernel(int* __restrict__ cnt, int* __restrict__ rowptr,
                            int* __restrict__ cursor, int n) {
    __shared__ int sh[1024];
    int tid = threadIdx.x;
    int chunk = (n + 1023) >> 10;
    int base = tid * chunk;
    int s = 0;
    for (int j = 0; j < chunk; j++) {
        int idx = base + j;
        if (idx < n) s += cnt[idx];
    }
    sh[tid] = s;
    __syncthreads();
    for (int off = 1; off < 1024; off <<= 1) {
        int v = (tid >= off) ? sh[tid - off] : 0;
        __syncthreads();
        sh[tid] += v;
        __syncthreads();
    }
    int run = sh[tid] - s;
    for (int j = 0; j < chunk; j++) {
        int idx = base + j;
        if (idx < n) {
            rowptr[idx] = run;
            cursor[idx] = run;
            run += cnt[idx];
            cnt[idx] = 0;
        }
    }
    if (tid == 1023) rowptr[n] = run;
}

__global__ void scatter_kernel(const int* __restrict__ src, const int* __restrict__ dst,
                               int* __restrict__ cursor, int* __restrict__ colsrc,
                               int* __restrict__ coldst, int e) {
    int t = blockIdx.x * blockDim.x + threadIdx.x;
    if (t < e) {
        int d = dst[t];
        int p = atomicAdd(&cursor[d], 1);
        colsrc[p] = src[t];
        coldst[p] = d;
    }
}

// ---------------- per-edge softmax numerators --------------------------------
template <int H>
__global__ void weight_kernel(const float* __restrict__ asrc, const float* __restrict__ adst,
                              const int* __restrict__ colsrc, const int* __restrict__ coldst,
                              float* __restrict__ wexp, int e) {
    int t = blockIdx.x * blockDim.x + threadIdx.x;
    if (t < e) {
        int s = colsrc[t], d = coldst[t];
#pragma unroll
        for (int h = 0; h < H; h++) {
            float ev = asrc[s * H + h] + adst[d * H + h];
            ev = ev > 0.f ? ev : 0.2f * ev;
            wexp[t * H + h] = __expf(ev);
        }
    }
}

// ---------------- bf16x3 tensor-core GEMM + fused alpha projection ----------
// C[M,256] = A[M,K] @ B[K,256]; A fp32 (split at staging), B pre-split.
// 128x128 CTA tile, BK=32, 8 warps (2x4), warp tile 64x32, m16n8k16 bf16 mma,
// 3-term split, term-major issue. DOUBLE-BUFFERED shared: one __syncthreads
// per tile; staging of tile t+1 overlaps the mma burst over tile t.
// Dynamic smem: 2 stages x (Ah|Al|Bh|Bl each 128x20 uint32) = 81920 B.
#define GARR 2560                 // uint32 per array (128 rows x 20)
#define GSTAGE (4 * GARR)         // uint32 per stage
#define GSMEM_BYTES (2 * GSTAGE * 4)

template <int H>
__global__ void __launch_bounds__(256, 2) gemm_bf16(
    const float* __restrict__ A,
    const uint32_t* __restrict__ Bth, const uint32_t* __restrict__ Btl,
    float* __restrict__ C, int M, int K,
    const float* __restrict__ a_s, const float* __restrict__ a_d,
    float* __restrict__ asrc, float* __restrict__ adst)
{
    extern __shared__ uint32_t sm[];

    const int tid  = threadIdx.x;
    const int lane = tid & 31;
    const int w    = tid >> 5;
    const int g    = lane >> 2;
    const int t    = lane & 3;
    const int wm   = w >> 2;
    const int wn   = w & 3;

    const int row0 = blockIdx.y * 128;
    const int col0 = blockIdx.x * 128;
    const int KW   = K >> 1;

    // staging indices
    const int ar   = tid >> 1;            // row 0..127
    const int ak16 = (tid & 1) << 4;      // A k base within tile: 0 or 16
    const int bk8  = (tid & 1) << 3;      // B kpair base: 0 or 8
    const bool a_ok = (row0 + ar) < M;

    const float*    Arow  = A + (size_t)(row0 + ar) * K + ak16;
    const uint32_t* Bhrow = Bth + (size_t)(col0 + ar) * KW + bk8;
    const uint32_t* Blrow = Btl + (size_t)(col0 + ar) * KW + bk8;

    float acc[4][4][4];
#pragma unroll
    for (int mt = 0; mt < 4; mt++)
#pragma unroll
        for (int nt = 0; nt < 4; nt++)
#pragma unroll
            for (int i = 0; i < 4; i++) acc[mt][nt][i] = 0.f;

    const float4 zf = make_float4(0.f, 0.f, 0.f, 0.f);
    float4 pa[4];
    uint4  pbh0, pbh1, pbl0, pbl1;

    // ---- load tile 0 into regs ----
#pragma unroll
    for (int i = 0; i < 4; i++)
        pa[i] = a_ok ? *(const float4*)(Arow + i * 4) : zf;
    pbh0 = *(const uint4*)(Bhrow);
    pbh1 = *(const uint4*)(Bhrow + 4);
    pbl0 = *(const uint4*)(Blrow);
    pbl1 = *(const uint4*)(Blrow + 4);

    // ---- store tile 0 to stage 0 ----
    {
        uint32_t* Ah = sm;
        uint32_t* Al = sm + GARR;
        uint32_t* Bh = sm + 2 * GARR;
        uint32_t* Bl = sm + 3 * GARR;
        uint32_t wh[8], wl[8];
#pragma unroll
        for (int i = 0; i < 4; i++) {
            wh[2 * i]     = bf16_pack_hi(pa[i].x, pa[i].y);
            wh[2 * i + 1] = bf16_pack_hi(pa[i].z, pa[i].w);
            wl[2 * i]     = bf16_pack_lo(pa[i].x, pa[i].y);
            wl[2 * i + 1] = bf16_pack_lo(pa[i].z, pa[i].w);
        }
        uint32_t* pA  = &Ah[ar * 20 + (ak16 >> 1)];
        uint32_t* pAl = &Al[ar * 20 + (ak16 >> 1)];
        *(uint4*)(pA)      = make_uint4(wh[0], wh[1], wh[2], wh[3]);
        *(uint4*)(pA + 4)  = make_uint4(wh[4], wh[5], wh[6], wh[7]);
        *(uint4*)(pAl)     = make_uint4(wl[0], wl[1], wl[2], wl[3]);
        *(uint4*)(pAl + 4) = make_uint4(wl[4], wl[5], wl[6], wl[7]);
        uint32_t* pB  = &Bh[ar * 20 + bk8];
        uint32_t* pBl = &Bl[ar * 20 + bk8];
        *(uint4*)(pB)      = pbh0;
        *(uint4*)(pB + 4)  = pbh1;
        *(uint4*)(pBl)     = pbl0;
        *(uint4*)(pBl + 4) = pbl1;
    }
    __syncthreads();

    for (int kt = 0; kt < K; kt += 32) {
        const int stage = (kt >> 5) & 1;
        uint32_t* base = sm + stage * GSTAGE;
        uint32_t* Ah = base;
        uint32_t* Al = base + GARR;
        uint32_t* Bh = base + 2 * GARR;
        uint32_t* Bl = base + 3 * GARR;

        const int ktn = kt + 32;
        const bool has_next = ktn < K;

        // ---- issue prefetch of tile t+1 (overlaps the mma burst below) ----
        if (has_next) {
#pragma unroll
            for (int i = 0; i < 4; i++)
                pa[i] = a_ok ? *(const float4*)(Arow + ktn + i * 4) : zf;
            int kwn = ktn >> 1;
            pbh0 = *(const uint4*)(Bhrow + kwn);
            pbh1 = *(const uint4*)(Bhrow + kwn + 4);
            pbl0 = *(const uint4*)(Blrow + kwn);
            pbl1 = *(const uint4*)(Blrow + kwn + 4);
        }

        // ---- mma burst over current stage (term-major, dep dist = 4) ----
#pragma unroll
        for (int kk = 0; kk < 2; kk++) {
            const int kb = kk * 8 + t;
            uint32_t bh[4][2], bl[4][2];
#pragma unroll
            for (int nt = 0; nt < 4; nt++) {
                int n = wn * 32 + nt * 8 + g;
                bh[nt][0] = Bh[n * 20 + kb];
                bh[nt][1] = Bh[n * 20 + kb + 4];
                bl[nt][0] = Bl[n * 20 + kb];
                bl[nt][1] = Bl[n * 20 + kb + 4];
            }
#pragma unroll
            for (int mt = 0; mt < 4; mt++) {
                int rb = wm * 64 + mt * 16 + g;
                uint32_t ah[4], al[4];
                ah[0] = Ah[rb * 20 + kb];
                ah[1] = Ah[(rb + 8) * 20 + kb];
                ah[2] = Ah[rb * 20 + kb + 4];
                ah[3] = Ah[(rb + 8) * 20 + kb + 4];
                al[0] = Al[rb * 20 + kb];
                al[1] = Al[(rb + 8) * 20 + kb];
                al[2] = Al[rb * 20 + kb + 4];
                al[3] = Al[(rb + 8) * 20 + kb + 4];
#pragma unroll
                for (int nt = 0; nt < 4; nt++)
                    mma_bf16(acc[mt][nt], ah[0], ah[1], ah[2], ah[3], bh[nt][0], bh[nt][1]);
#pragma unroll
                for (int nt = 0; nt < 4; nt++)
                    mma_bf16(acc[mt][nt], ah[0], ah[1], ah[2], ah[3], bl[nt][0], bl[nt][1]);
#pragma unroll
                for (int nt = 0; nt < 4; nt++)
                    mma_bf16(acc[mt][nt], al[0], al[1], al[2], al[3], bh[nt][0], bh[nt][1]);
            }
        }

        // ---- store tile t+1 into the other stage ----
        if (has_next) {
            uint32_t* nbase = sm + (stage ^ 1) * GSTAGE;
            uint32_t* nAh = nbase;
            uint32_t* nAl = nbase + GARR;
            uint32_t* nBh = nbase + 2 * GARR;
            uint32_t* nBl = nbase + 3 * GARR;
            uint32_t wh[8], wl[8];
#pragma unroll
            for (int i = 0; i < 4; i++) {
                wh[2 * i]     = bf16_pack_hi(pa[i].x, pa[i].y);
                wh[2 * i + 1] = bf16_pack_hi(pa[i].z, pa[i].w);
                wl[2 * i]     = bf16_pack_lo(pa[i].x, pa[i].y);
                wl[2 * i + 1] = bf16_pack_lo(pa[i].z, pa[i].w);
            }
            uint32_t* pA  = &nAh[ar * 20 + (ak16 >> 1)];
            uint32_t* pAl = &nAl[ar * 20 + (ak16 >> 1)];
            *(uint4*)(pA)      = make_uint4(wh[0], wh[1], wh[2], wh[3]);
            *(uint4*)(pA + 4)  = make_uint4(wh[4], wh[5], wh[6], wh[7]);
            *(uint4*)(pAl)     = make_uint4(wl[0], wl[1], wl[2], wl[3]);
            *(uint4*)(pAl + 4) = make_uint4(wl[4], wl[5], wl[6], wl[7]);
            uint32_t* pB  = &nBh[ar * 20 + bk8];
            uint32_t* pBl = &nBl[ar * 20 + bk8];
            *(uint4*)(pB)      = pbh0;
            *(uint4*)(pB + 4)  = pbh1;
            *(uint4*)(pBl)     = pbl0;
            *(uint4*)(pBl + 4) = pbl1;
        }
        __syncthreads();
    }

    // ---- epilogue 1: store C tile ----
#pragma unroll
    for (int mt = 0; mt < 4; mt++) {
        int r0 = row0 + wm * 64 + mt * 16 + g;
        int r1 = r0 + 8;
#pragma unroll
        for (int nt = 0; nt < 4; nt++) {
            int col = col0 + wn * 32 + nt * 8 + 2 * t;
            if (r0 < M)
                *(float2*)(C + (size_t)r0 * NF + col) = make_float2(acc[mt][nt][0], acc[mt][nt][1]);
            if (r1 < M)
                *(float2*)(C + (size_t)r1 * NF + col) = make_float2(acc[mt][nt][2], acc[mt][nt][3]);
        }
    }

    // ---- epilogue 2: fused alpha projection (atomic; zeroed by hist) -------
    {
        float asv[4][2], adv[4][2];
#pragma unroll
        for (int nt = 0; nt < 4; nt++)
#pragma unroll
            for (int i = 0; i < 2; i++) {
                int gcol = col0 + wn * 32 + nt * 8 + 2 * t + i;
                asv[nt][i] = a_s[gcol];
                adv[nt][i] = a_d[gcol];
            }
        const int hd = (H == 4) ? ((col0 + wn * 32) >> 6) : 0;
#pragma unroll
        for (int mt = 0; mt < 4; mt++) {
            float sa0 = 0.f, sd0 = 0.f, sa1 = 0.f, sd1 = 0.f;
#pragma unroll
            for (int nt = 0; nt < 4; nt++)
#pragma unroll
                for (int i = 0; i < 2; i++) {
                    sa0 += acc[mt][nt][i]     * asv[nt][i];
                    sd0 += acc[mt][nt][i]     * adv[nt][i];
                    sa1 += acc[mt][nt][2 + i] * asv[nt][i];
                    sd1 += acc[mt][nt][2 + i] * adv[nt][i];
                }
#pragma unroll
            for (int o = 1; o <= 2; o <<= 1) {
                sa0 += __shfl_xor_sync(0xffffffffu, sa0, o);
                sd0 += __shfl_xor_sync(0xffffffffu, sd0, o);
                sa1 += __shfl_xor_sync(0xffffffffu, sa1, o);
                sd1 += __shfl_xor_sync(0xffffffffu, sd1, o);
            }
            if (t == 0) {
                int r0 = row0 + wm * 64 + mt * 16 + g;
                int r1 = r0 + 8;
                if (r0 < M) {
                    atomicAdd(&asrc[r0 * H + hd], sa0);
                    atomicAdd(&adst[r0 * H + hd], sd0);
                }
                if (r1 < M) {
                    atomicAdd(&asrc[r1 * H + hd], sa1);
                    atomicAdd(&adst[r1 * H + hd], sd1);
                }
            }
        }
    }
}

// ---------------- block-sum helper (64 threads, 2 warps) ---------------------
__device__ __forceinline__ float block_sum64(float v, float* red) {
#pragma unroll
    for (int o = 16; o > 0; o >>= 1) v += __shfl_xor_sync(0xffffffffu, v, o);
    int wid = threadIdx.x >> 5;
    if ((threadIdx.x & 31) == 0) red[wid] = v;
    __syncthreads();
    float s = red[0] + red[1];
    __syncthreads();
    return s;
}

// ---------------- fused aggregation + bias + LN + ELU -----------------------
template <int H>
__global__ void __launch_bounds__(64) agg_kernel(
    const float4* __restrict__ hfeat4,
    const float* __restrict__ asrc, const float* __restrict__ adst,
    const int* __restrict__ rowptr, const int* __restrict__ colsrc,
    const float* __restrict__ wexp,
    const float4* __restrict__ bias4, const float4* __restrict__ lnw4,
    const float4* __restrict__ lnb4, float4* __restrict__ out4)
{
    __shared__ float red[2];

    int i   = blockIdx.x;
    int tid = threadIdx.x;
    int head = (H == 4) ? (tid >> 4) : 0;

    float e0 = asrc[i * H + head] + adst[i * H + head];
    e0 = e0 > 0.f ? e0 : 0.2f * e0;
    float w0 = __expf(e0);
    float den = w0;
    float4 hv = hfeat4[(size_t)i * 64 + tid];
    float4 acc = make_float4(w0 * hv.x, w0 * hv.y, w0 * hv.z, w0 * hv.w);

    int beg = rowptr[i], end = rowptr[i + 1];
    int p = beg;
    for (; p + 4 <= end; p += 4) {
        int s0 = colsrc[p], s1 = colsrc[p + 1], s2 = colsrc[p + 2], s3 = colsrc[p + 3];
        float w_0 = wexp[(p + 0) * H + head];
        float w_1 = wexp[(p + 1) * H + head];
        float w_2 = wexp[(p + 2) * H + head];
        float w_3 = wexp[(p + 3) * H + head];
        float4 h0 = hfeat4[(size_t)s0 * 64 + tid];
        float4 h1 = hfeat4[(size_t)s1 * 64 + tid];
        float4 h2 = hfeat4[(size_t)s2 * 64 + tid];
        float4 h3 = hfeat4[(size_t)s3 * 64 + tid];
        den += (w_0 + w_1) + (w_2 + w_3);
        acc.x += w_0 * h0.x + w_1 * h1.x + w_2 * h2.x + w_3 * h3.x;
        acc.y += w_0 * h0.y + w_1 * h1.y + w_2 * h2.y + w_3 * h3.y;
        acc.z += w_0 * h0.z + w_1 * h1.z + w_2 * h2.z + w_3 * h3.z;
        acc.w += w_0 * h0.w + w_1 * h1.w + w_2 * h2.w + w_3 * h3.w;
    }
    for (; p < end; p++) {
        int s0 = colsrc[p];
        float wv = wexp[p * H + head];
        float4 h0 = hfeat4[(size_t)s0 * 64 + tid];
        den += wv;
        acc.x += wv * h0.x; acc.y += wv * h0.y; acc.z += wv * h0.z; acc.w += wv * h0.w;
    }

    float4 bv = bias4[tid];
    float inv = 1.f / den;
    float4 v = make_float4(acc.x * inv + bv.x, acc.y * inv + bv.y,
                           acc.z * inv + bv.z, acc.w * inv + bv.w);

    float mean = block_sum64(v.x + v.y + v.z + v.w, red) * (1.f / NF);
    float4 dl = make_float4(v.x - mean, v.y - mean, v.z - mean, v.w - mean);
    float var = block_sum64(dl.x * dl.x + dl.y * dl.y + dl.z * dl.z + dl.w * dl.w, red)
                * (1.f / NF);
    float rs = rsqrtf(var + 1e-5f);
    float4 wv4 = lnw4[tid];
    float4 bb = lnb4[tid];
    float4 y;
    y.x = dl.x * rs * wv4.x + bb.x;
    y.y = dl.y * rs * wv4.y + bb.y;
    y.z = dl.z * rs * wv4.z + bb.z;
    y.w = dl.w * rs * wv4.w + bb.w;
    y.x = y.x > 0.f ? y.x : expm1f(y.x);
    y.y = y.y > 0.f ? y.y : expm1f(y.y);
    y.z = y.z > 0.f ? y.z : expm1f(y.z);
    y.w = y.w > 0.f ? y.w : expm1f(y.w);
    out4[(size_t)i * 64 + tid] = y;
}

// ---------------- launch ----------------------------------------------------
extern "C" void kernel_launch(void* const* d_in, const int* in_sizes, int n_in,
                              void* d_out, int out_size) {
    const float* x    = (const float*)d_in[0];
    const int*   ei   = (const int*)d_in[1];
    const float* W0   = (const float*)d_in[2];
    const float* as0  = (const float*)d_in[3];
    const float* ad0  = (const float*)d_in[4];
    const float* b0   = (const float*)d_in[5];
    const float* lnw0 = (const float*)d_in[6];
    const float* lnb0 = (const float*)d_in[7];
    const float* W1   = (const float*)d_in[8];
    const float* as1  = (const float*)d_in[9];
    const float* ad1  = (const float*)d_in[10];
    const float* b1   = (const float*)d_in[11];
    const float* lnw1 = (const float*)d_in[12];
    const float* lnb1 = (const float*)d_in[13];
    const float* W2   = (const float*)d_in[14];
    const float* as2  = (const float*)d_in[15];
    const float* ad2  = (const float*)d_in[16];
    const float* b2   = (const float*)d_in[17];
    const float* lnw2 = (const float*)d_in[18];
    const float* lnb2 = (const float*)d_in[19];
    float* out = (float*)d_out;

    int n = in_sizes[0] / 512;   // 50000
    int e = in_sizes[1] / 2;     // 800000
    const int* src = ei;
    const int* dst = ei + e;

    float *ph, *pbuf, *palpha, *pwexp;
    int *pcnt, *prow, *pcur, *pcol, *pcds;
    uint32_t *pw0h, *pw0l, *pw1h, *pw1l, *pw2h, *pw2l;
    cudaGetSymbolAddress((void**)&ph, g_h);
    cudaGetSymbolAddress((void**)&pbuf, g_buf);
    cudaGetSymbolAddress((void**)&palpha, g_alpha);
    cudaGetSymbolAddress((void**)&pwexp, g_wexp);
    cudaGetSymbolAddress((void**)&pcnt, g_cnt);
    cudaGetSymbolAddress((void**)&prow, g_rowptr);
    cudaGetSymbolAddress((void**)&pcur, g_cursor);
    cudaGetSymbolAddress((void**)&pcol, g_colsrc);
    cudaGetSymbolAddress((void**)&pcds, g_coldst);
    cudaGetSymbolAddress((void**)&pw0h, g_w0h);
    cudaGetSymbolAddress((void**)&pw0l, g_w0l);
    cudaGetSymbolAddress((void**)&pw1h, g_w1h);
    cudaGetSymbolAddress((void**)&pw1l, g_w1l);
    cudaGetSymbolAddress((void**)&pw2h, g_w2h);
    cudaGetSymbolAddress((void**)&pw2l, g_w2l);

    float* pas0 = palpha + (size_t)0 * MAXN * 4;
    float* pad0 = palpha + (size_t)1 * MAXN * 4;
    float* pas1 = palpha + (size_t)2 * MAXN * 4;
    float* pad1 = palpha + (size_t)3 * MAXN * 4;
    float* pas2 = palpha + (size_t)4 * MAXN * 4;
    float* pad2 = palpha + (size_t)5 * MAXN * 4;

    // allow 80KB dynamic smem for the double-buffered GEMM (idempotent)
    cudaFuncSetAttribute(gemm_bf16<4>, cudaFuncAttributeMaxDynamicSharedMemorySize, GSMEM_BYTES);
    cudaFuncSetAttribute(gemm_bf16<1>, cudaFuncAttributeMaxDynamicSharedMemorySize, GSMEM_BYTES);

    const int TPB = 256;
    const int egrid = (e + TPB - 1) / TPB;
    hist_kernel<<<egrid, TPB>>>(dst, pcnt, e, palpha, W0, W1, W2,
                                pw0h, pw0l, pw1h, pw1l, pw2h, pw2l);
    scan_kernel<<<1, 1024>>>(pcnt, prow, pcur, n);
    scatter_kernel<<<egrid, TPB>>>(src, dst, pcur, pcol, pcds, e);

    dim3 ggrid(NF / 128, (n + 127) / 128);

    // layer 0: GATConv(512 -> 4x64)
    gemm_bf16<4><<<ggrid, 256, GSMEM_BYTES>>>(x, pw0h, pw0l, ph, n, 512, as0, ad0, pas0, pad0);
    weight_kernel<4><<<egrid, TPB>>>(pas0, pad0, pcol, pcds, pwexp, e);
    agg_kernel<4><<<n, 64>>>((const float4*)ph, pas0, pad0, prow, pcol, pwexp,
                             (const float4*)b0, (const float4*)lnw0,
                             (const float4*)lnb0, (float4*)pbuf);

    // layer 1: GATConv(256 -> 4x64)
    gemm_bf16<4><<<ggrid, 256, GSMEM_BYTES>>>(pbuf, pw1h, pw1l, ph, n, 256, as1, ad1, pas1, pad1);
    weight_kernel<4><<<egrid, TPB>>>(pas1, pad1, pcol, pcds, pwexp, e);
    agg_kernel<4><<<n, 64>>>((const float4*)ph, pas1, pad1, prow, pcol, pwexp,
                             (const float4*)b1, (const float4*)lnw1,
                             (const float4*)lnb1, (float4*)pbuf);

    // layer 2: GATConv(256 -> 1x256)
    gemm_bf16<1><<<ggrid, 256, GSMEM_BYTES>>>(pbuf, pw2h, pw2l, ph, n, 256, as2, ad2, pas2, pad2);
    weight_kernel<1><<<egrid, TPB>>>(pas2, pad2, pcol, pcds, pwexp, e);
    agg_kernel<1><<<n, 64>>>((const float4*)ph, pas2, pad2, prow, pcol, pwexp,
                             (const float4*)b2, (const float4*)lnw2,
                             (const float4*)lnb2, (float4*)out);
}

// round 14
// speedup vs baseline: 1.1044x; 1.0112x over previous
#include <cuda_runtime.h>
#include <cuda_bf16.h>
#include <stdint.h>
#include <math.h>

#define MAXN 50000
#define MAXE 800000
#define NF 256

// ---------------- scratch (device globals; no allocation allowed) ----------
__device__ float g_h[(size_t)MAXN * NF];     // GEMM fp32 output (for agg gather)
__device__ float g_alpha[(size_t)6 * MAXN * 4];
__device__ float g_wexp[(size_t)MAXE * 4];
__device__ int   g_cnt[MAXN];
__device__ int   g_rowptr[MAXN + 1];
__device__ int   g_cursor[MAXN];
__device__ int   g_colsrc[MAXE];
__device__ int   g_coldst[MAXE];
// pre-split activations: [row][kpair] packed bf16x2
__device__ uint32_t g_xh[(size_t)MAXN * 256], g_xl[(size_t)MAXN * 256];   // x: K=512
__device__ uint32_t g_yh[(size_t)MAXN * 128], g_yl[(size_t)MAXN * 128];   // layer outs
// pre-transposed, bf16-split weights: [n][kpair] packed bf16x2
__device__ uint32_t g_w0h[256 * 256], g_w0l[256 * 256];
__device__ uint32_t g_w1h[256 * 128], g_w1l[256 * 128];
__device__ uint32_t g_w2h[256 * 128], g_w2l[256 * 128];

// ---------------- bf16 split helpers ----------------------------------------
__device__ __forceinline__ uint32_t bf16_pack_hi(float f0, float f1) {
    __nv_bfloat16 h0 = __float2bfloat16(f0);
    __nv_bfloat16 h1 = __float2bfloat16(f1);
    return (uint32_t)__bfloat16_as_ushort(h0) | ((uint32_t)__bfloat16_as_ushort(h1) << 16);
}
__device__ __forceinline__ uint32_t bf16_pack_lo(float f0, float f1) {
    __nv_bfloat16 h0 = __float2bfloat16(f0);
    __nv_bfloat16 h1 = __float2bfloat16(f1);
    __nv_bfloat16 l0 = __float2bfloat16(f0 - __bfloat162float(h0));
    __nv_bfloat16 l1 = __float2bfloat16(f1 - __bfloat162float(h1));
    return (uint32_t)__bfloat16_as_ushort(l0) | ((uint32_t)__bfloat16_as_ushort(l1) << 16);
}

__device__ __forceinline__ void mma_bf16(float c[4],
                                         uint32_t a0, uint32_t a1, uint32_t a2, uint32_t a3,
                                         uint32_t b0, uint32_t b1) {
    asm volatile(
        "mma.sync.aligned.m16n8k16.row.col.f32.bf16.bf16.f32 "
        "{%0,%1,%2,%3}, {%4,%5,%6,%7}, {%8,%9}, {%0,%1,%2,%3};"
        : "+f"(c[0]), "+f"(c[1]), "+f"(c[2]), "+f"(c[3])
        : "r"(a0), "r"(a1), "r"(a2), "r"(a3), "r"(b0), "r"(b1));
}

__device__ __forceinline__ uint32_t smem_u32(const void* p) {
    uint32_t a;
    asm("{ .reg .u64 t; cvta.to.shared.u64 t, %1; cvt.u32.u64 %0, t; }" : "=r"(a) : "l"(p));
    return a;
}
__device__ __forceinline__ void cp16(uint32_t d, const uint32_t* s, bool p) {
    int sz = p ? 16 : 0;
    asm volatile("cp.async.cg.shared.global [%0], [%1], 16, %2;"
                 :: "r"(d), "l"(s), "r"(sz) : "memory");
}
#define CP_COMMIT() asm volatile("cp.async.commit_group;" ::: "memory")
#define CP_WAIT2()  asm volatile("cp.async.wait_group 2;" ::: "memory")

// ---------------- hist + alpha zero + weight prep + x split (fused) ---------
__global__ void hist_kernel(const int* __restrict__ dst, int* __restrict__ cnt, int e,
                            float* __restrict__ alpha,
                            const float* __restrict__ W0, const float* __restrict__ W1,
                            const float* __restrict__ W2,
                            uint32_t* __restrict__ w0h, uint32_t* __restrict__ w0l,
                            uint32_t* __restrict__ w1h, uint32_t* __restrict__ w1l,
                            uint32_t* __restrict__ w2h, uint32_t* __restrict__ w2l,
                            const float2* __restrict__ x2,
                            uint32_t* __restrict__ xh, uint32_t* __restrict__ xl,
                            int xtotal) {
    int t = blockIdx.x * blockDim.x + threadIdx.x;
    int nthr = gridDim.x * blockDim.x;
    if (t < e) atomicAdd(&cnt[dst[t]], 1);
    // zero alpha accumulators (GEMM epilogue accumulates atomically; needed per replay)
    const int atot = 6 * MAXN * 4;
    for (int i = t; i < atot; i += nthr) alpha[i] = 0.f;
    // weight transpose + split
    const int T0 = 256 * 256, T1 = 256 * 128;
    if (t < T0) {
        int n = t >> 8, kp = t & 255;
        float f0 = W0[(2 * kp) * 256 + n];
        float f1 = W0[(2 * kp + 1) * 256 + n];
        w0h[n * 256 + kp] = bf16_pack_hi(f0, f1);
        w0l[n * 256 + kp] = bf16_pack_lo(f0, f1);
    } else if (t < T0 + T1) {
        int id = t - T0;
        int n = id >> 7, kp = id & 127;
        float f0 = W1[(2 * kp) * 256 + n];
        float f1 = W1[(2 * kp + 1) * 256 + n];
        w1h[n * 128 + kp] = bf16_pack_hi(f0, f1);
        w1l[n * 128 + kp] = bf16_pack_lo(f0, f1);
    } else if (t < T0 + 2 * T1) {
        int id = t - T0 - T1;
        int n = id >> 7, kp = id & 127;
        float f0 = W2[(2 * kp) * 256 + n];
        float f1 = W2[(2 * kp + 1) * 256 + n];
        w2h[n * 128 + kp] = bf16_pack_hi(f0, f1);
        w2l[n * 128 + kp] = bf16_pack_lo(f0, f1);
    }
    // x split (grid-stride; xtotal = n*256 kpairs, contiguous)
    for (int i = t; i < xtotal; i += nthr) {
        float2 f = x2[i];
        xh[i] = bf16_pack_hi(f.x, f.y);
        xl[i] = bf16_pack_lo(f.x, f.y);
    }
}

__global__ void scan_kernel(int* __restrict__ cnt, int* __restrict__ rowptr,
                            int* __restrict__ cursor, int n) {
    __shared__ int sh[1024];
    int tid = threadIdx.x;
    int chunk = (n + 1023) >> 10;
    int base = tid * chunk;
    int s = 0;
    for (int j = 0; j < chunk; j++) {
        int idx = base + j;
        if (idx < n) s += cnt[idx];
    }
    sh[tid] = s;
    __syncthreads();
    for (int off = 1; off < 1024; off <<= 1) {
        int v = (tid >= off) ? sh[tid - off] : 0;
        __syncthreads();
        sh[tid] += v;
        __syncthreads();
    }
    int run = sh[tid] - s;
    for (int j = 0; j < chunk; j++) {
        int idx = base + j;
        if (idx < n) {
            rowptr[idx] = run;
            cursor[idx] = run;
            run += cnt[idx];
            cnt[idx] = 0;
        }
    }
    if (tid == 1023) rowptr[n] = run;
}

__global__ void scatter_kernel(const int* __restrict__ src, const int* __restrict__ dst,
                               int* __restrict__ cursor, int* __restrict__ colsrc,
                               int* __restrict__ coldst, int e) {
    int t = blockIdx.x * blockDim.x + threadIdx.x;
    if (t < e) {
        int d = dst[t];
        int p = atomicAdd(&cursor[d], 1);
        colsrc[p] = src[t];
        coldst[p] = d;
    }
}

// ---------------- per-edge softmax numerators --------------------------------
template <int H>
__global__ void weight_kernel(const float* __restrict__ asrc, const float* __restrict__ adst,
                              const int* __restrict__ colsrc, const int* __restrict__ coldst,
                              float* __restrict__ wexp, int e) {
    int t = blockIdx.x * blockDim.x + threadIdx.x;
    if (t < e) {
        int s = colsrc[t], d = coldst[t];
#pragma unroll
        for (int h = 0; h < H; h++) {
            float ev = asrc[s * H + h] + adst[d * H + h];
            ev = ev > 0.f ? ev : 0.2f * ev;
            wexp[t * H + h] = __expf(ev);
        }
    }
}

// ---------------- cp.async-pipelined bf16x3 tensor-core GEMM ----------------
// C[M,256] = A[M,K] @ B[K,256]; BOTH operands pre-split in DRAM [major][kpair].
// CTA 128x128, 8 warps (2x4), warp tile 64x32, m16n8k16 bf16 mma, 3-term split,
// term-major issue. 4-stage cp.async pipeline, BK=16:
//   per iter: wait_group 2 -> syncthreads -> issue tile t+3 -> mma tile t.
// Stage layout: 4 arrays (Ah|Al|Bh|Bl), each 128 rows x 12 uint32 (8 data+4 pad),
// conflict-free for fragment loads. Smem = 4 stages x 24KB = 96KB.
#define ARRW  1536                 // 128*12 uint32
#define STGW  (4 * ARRW)
#define NSTG  4
#define GSMEM (NSTG * STGW * 4)    // 98304 B

template <int H>
__global__ void __launch_bounds__(256, 2) gemm_bf16(
    const uint32_t* __restrict__ Ath, const uint32_t* __restrict__ Atl,
    const uint32_t* __restrict__ Bth, const uint32_t* __restrict__ Btl,
    float* __restrict__ C, int M, int K,
    const float* __restrict__ a_s, const float* __restrict__ a_d,
    float* __restrict__ asrc, float* __restrict__ adst)
{
    extern __shared__ uint32_t sm[];
    const uint32_t smb = smem_u32(sm);

    const int tid  = threadIdx.x;
    const int lane = tid & 31;
    const int w    = tid >> 5;
    const int g    = lane >> 2;
    const int t    = lane & 3;
    const int wm   = w >> 2;
    const int wn   = w & 3;

    const int row0 = blockIdx.y * 128;
    const int col0 = blockIdx.x * 128;
    const int KW   = K >> 1;           // kpairs per row
    const int NT   = K >> 4;           // 16-K tiles

    // staging: thread -> (row r, 16B half hh); 4 cp.async per stage per thread
    const int r  = tid >> 1;
    const int hh = tid & 1;
    const bool aok = (row0 + r) < M;
    const int arow = aok ? (row0 + r) : (M - 1);
    const uint32_t* gAh = Ath + (size_t)arow * KW + hh * 4;
    const uint32_t* gAl = Atl + (size_t)arow * KW + hh * 4;
    const uint32_t* gBh = Bth + (size_t)(col0 + r) * KW + hh * 4;
    const uint32_t* gBl = Btl + (size_t)(col0 + r) * KW + hh * 4;
    const uint32_t sdst = smb + (uint32_t)(r * 12 + hh * 4) * 4;

    float acc[4][4][4];
#pragma unroll
    for (int mt = 0; mt < 4; mt++)
#pragma unroll
        for (int nt = 0; nt < 4; nt++)
#pragma unroll
            for (int i = 0; i < 4; i++) acc[mt][nt][i] = 0.f;

    // prologue: issue tiles 0..2
#pragma unroll
    for (int s = 0; s < 3; s++) {
        uint32_t so = sdst + (uint32_t)(s * STGW) * 4;
        int kp = s * 8;
        cp16(so,                gAh + kp, aok);
        cp16(so + ARRW * 4,     gAl + kp, aok);
        cp16(so + 2 * ARRW * 4, gBh + kp, true);
        cp16(so + 3 * ARRW * 4, gBl + kp, true);
        CP_COMMIT();
    }

    for (int tt = 0; tt < NT; tt++) {
        CP_WAIT2();           // tile tt's (per-thread) copies complete
        __syncthreads();      // join: all threads' tile-tt data visible; slot (tt+3)&3 free

        int nx = tt + 3;
        if (nx < NT) {
            uint32_t so = sdst + (uint32_t)((nx & 3) * STGW) * 4;
            int kp = nx * 8;
            cp16(so,                gAh + kp, aok);
            cp16(so + ARRW * 4,     gAl + kp, aok);
            cp16(so + 2 * ARRW * 4, gBh + kp, true);
            cp16(so + 3 * ARRW * 4, gBl + kp, true);
        }
        CP_COMMIT();          // always commit (empty in tail) to keep wait semantics

        // ---- mma burst on slot tt&3 (term-major, dep dist = 4) ----
        const uint32_t* Ah = sm + (tt & 3) * STGW;
        const uint32_t* Al = Ah + ARRW;
        const uint32_t* Bh = Ah + 2 * ARRW;
        const uint32_t* Bl = Ah + 3 * ARRW;
        const int kb = t;
        uint32_t bh[4][2], bl[4][2];
#pragma unroll
        for (int nt = 0; nt < 4; nt++) {
            int n = wn * 32 + nt * 8 + g;
            bh[nt][0] = Bh[n * 12 + kb];
            bh[nt][1] = Bh[n * 12 + kb + 4];
            bl[nt][0] = Bl[n * 12 + kb];
            bl[nt][1] = Bl[n * 12 + kb + 4];
        }
#pragma unroll
        for (int mt = 0; mt < 4; mt++) {
            int rb = wm * 64 + mt * 16 + g;
            uint32_t ah[4], al[4];
            ah[0] = Ah[rb * 12 + kb];
            ah[1] = Ah[(rb + 8) * 12 + kb];
            ah[2] = Ah[rb * 12 + kb + 4];
            ah[3] = Ah[(rb + 8) * 12 + kb + 4];
            al[0] = Al[rb * 12 + kb];
            al[1] = Al[(rb + 8) * 12 + kb];
            al[2] = Al[rb * 12 + kb + 4];
            al[3] = Al[(rb + 8) * 12 + kb + 4];
#pragma unroll
            for (int nt = 0; nt < 4; nt++)
                mma_bf16(acc[mt][nt], ah[0], ah[1], ah[2], ah[3], bh[nt][0], bh[nt][1]);
#pragma unroll
            for (int nt = 0; nt < 4; nt++)
                mma_bf16(acc[mt][nt], ah[0], ah[1], ah[2], ah[3], bl[nt][0], bl[nt][1]);
#pragma unroll
            for (int nt = 0; nt < 4; nt++)
                mma_bf16(acc[mt][nt], al[0], al[1], al[2], al[3], bh[nt][0], bh[nt][1]);
        }
    }

    // ---- epilogue 1: store C tile ----
#pragma unroll
    for (int mt = 0; mt < 4; mt++) {
        int r0 = row0 + wm * 64 + mt * 16 + g;
        int r1 = r0 + 8;
#pragma unroll
        for (int nt = 0; nt < 4; nt++) {
            int col = col0 + wn * 32 + nt * 8 + 2 * t;
            if (r0 < M)
                *(float2*)(C + (size_t)r0 * NF + col) = make_float2(acc[mt][nt][0], acc[mt][nt][1]);
            if (r1 < M)
                *(float2*)(C + (size_t)r1 * NF + col) = make_float2(acc[mt][nt][2], acc[mt][nt][3]);
        }
    }

    // ---- epilogue 2: fused alpha projection (atomic; zeroed by hist) -------
    {
        float asv[4][2], adv[4][2];
#pragma unroll
        for (int nt = 0; nt < 4; nt++)
#pragma unroll
            for (int i = 0; i < 2; i++) {
                int gcol = col0 + wn * 32 + nt * 8 + 2 * t + i;
                asv[nt][i] = a_s[gcol];
                adv[nt][i] = a_d[gcol];
            }
        const int hd = (H == 4) ? ((col0 + wn * 32) >> 6) : 0;
#pragma unroll
        for (int mt = 0; mt < 4; mt++) {
            float sa0 = 0.f, sd0 = 0.f, sa1 = 0.f, sd1 = 0.f;
#pragma unroll
            for (int nt = 0; nt < 4; nt++)
#pragma unroll
                for (int i = 0; i < 2; i++) {
                    sa0 += acc[mt][nt][i]     * asv[nt][i];
                    sd0 += acc[mt][nt][i]     * adv[nt][i];
                    sa1 += acc[mt][nt][2 + i] * asv[nt][i];
                    sd1 += acc[mt][nt][2 + i] * adv[nt][i];
                }
#pragma unroll
            for (int o = 1; o <= 2; o <<= 1) {
                sa0 += __shfl_xor_sync(0xffffffffu, sa0, o);
                sd0 += __shfl_xor_sync(0xffffffffu, sd0, o);
                sa1 += __shfl_xor_sync(0xffffffffu, sa1, o);
                sd1 += __shfl_xor_sync(0xffffffffu, sd1, o);
            }
            if (t == 0) {
                int r0 = row0 + wm * 64 + mt * 16 + g;
                int r1 = r0 + 8;
                if (r0 < M) {
                    atomicAdd(&asrc[r0 * H + hd], sa0);
                    atomicAdd(&adst[r0 * H + hd], sd0);
                }
                if (r1 < M) {
                    atomicAdd(&asrc[r1 * H + hd], sa1);
                    atomicAdd(&adst[r1 * H + hd], sd1);
                }
            }
        }
    }
}

// ---------------- block-sum helper (64 threads, 2 warps) ---------------------
__device__ __forceinline__ float block_sum64(float v, float* red) {
#pragma unroll
    for (int o = 16; o > 0; o >>= 1) v += __shfl_xor_sync(0xffffffffu, v, o);
    int wid = threadIdx.x >> 5;
    if ((threadIdx.x & 31) == 0) red[wid] = v;
    __syncthreads();
    float s = red[0] + red[1];
    __syncthreads();
    return s;
}

// ---------------- fused aggregation + bias + LN + ELU -----------------------
// SPLIT=true: write bf16 hi/lo split (next layer's GEMM input).
// SPLIT=false: write fp32 (final output).
template <int H, bool SPLIT>
__global__ void __launch_bounds__(64) agg_kernel(
    const float4* __restrict__ hfeat4,
    const float* __restrict__ asrc, const float* __restrict__ adst,
    const int* __restrict__ rowptr, const int* __restrict__ colsrc,
    const float* __restrict__ wexp,
    const float4* __restrict__ bias4, const float4* __restrict__ lnw4,
    const float4* __restrict__ lnb4,
    float4* __restrict__ out4,
    uint32_t* __restrict__ yh, uint32_t* __restrict__ yl)
{
    __shared__ float red[2];

    int i   = blockIdx.x;
    int tid = threadIdx.x;
    int head = (H == 4) ? (tid >> 4) : 0;

    float e0 = asrc[i * H + head] + adst[i * H + head];
    e0 = e0 > 0.f ? e0 : 0.2f * e0;
    float w0 = __expf(e0);
    float den = w0;
    float4 hv = hfeat4[(size_t)i * 64 + tid];
    float4 acc = make_float4(w0 * hv.x, w0 * hv.y, w0 * hv.z, w0 * hv.w);

    int beg = rowptr[i], end = rowptr[i + 1];
    int p = beg;
    for (; p + 4 <= end; p += 4) {
        int s0 = colsrc[p], s1 = colsrc[p + 1], s2 = colsrc[p + 2], s3 = colsrc[p + 3];
        float w_0 = wexp[(p + 0) * H + head];
        float w_1 = wexp[(p + 1) * H + head];
        float w_2 = wexp[(p + 2) * H + head];
        float w_3 = wexp[(p + 3) * H + head];
        float4 h0 = hfeat4[(size_t)s0 * 64 + tid];
        float4 h1 = hfeat4[(size_t)s1 * 64 + tid];
        float4 h2 = hfeat4[(size_t)s2 * 64 + tid];
        float4 h3 = hfeat4[(size_t)s3 * 64 + tid];
        den += (w_0 + w_1) + (w_2 + w_3);
        acc.x += w_0 * h0.x + w_1 * h1.x + w_2 * h2.x + w_3 * h3.x;
        acc.y += w_0 * h0.y + w_1 * h1.y + w_2 * h2.y + w_3 * h3.y;
        acc.z += w_0 * h0.z + w_1 * h1.z + w_2 * h2.z + w_3 * h3.z;
        acc.w += w_0 * h0.w + w_1 * h1.w + w_2 * h2.w + w_3 * h3.w;
    }
    for (; p < end; p++) {
        int s0 = colsrc[p];
        float wv = wexp[p * H + head];
        float4 h0 = hfeat4[(size_t)s0 * 64 + tid];
        den += wv;
        acc.x += wv * h0.x; acc.y += wv * h0.y; acc.z += wv * h0.z; acc.w += wv * h0.w;
    }

    float4 bv = bias4[tid];
    float inv = 1.f / den;
    float4 v = make_float4(acc.x * inv + bv.x, acc.y * inv + bv.y,
                           acc.z * inv + bv.z, acc.w * inv + bv.w);

    float mean = block_sum64(v.x + v.y + v.z + v.w, red) * (1.f / NF);
    float4 dl = make_float4(v.x - mean, v.y - mean, v.z - mean, v.w - mean);
    float var = block_sum64(dl.x * dl.x + dl.y * dl.y + dl.z * dl.z + dl.w * dl.w, red)
                * (1.f / NF);
    float rs = rsqrtf(var + 1e-5f);
    float4 wv4 = lnw4[tid];
    float4 bb = lnb4[tid];
    float4 y;
    y.x = dl.x * rs * wv4.x + bb.x;
    y.y = dl.y * rs * wv4.y + bb.y;
    y.z = dl.z * rs * wv4.z + bb.z;
    y.w = dl.w * rs * wv4.w + bb.w;
    y.x = y.x > 0.f ? y.x : expm1f(y.x);
    y.y = y.y > 0.f ? y.y : expm1f(y.y);
    y.z = y.z > 0.f ? y.z : expm1f(y.z);
    y.w = y.w > 0.f ? y.w : expm1f(y.w);

    if (SPLIT) {
        uint2 hi, lo;
        hi.x = bf16_pack_hi(y.x, y.y);
        hi.y = bf16_pack_hi(y.z, y.w);
        lo.x = bf16_pack_lo(y.x, y.y);
        lo.y = bf16_pack_lo(y.z, y.w);
        *(uint2*)(yh + (size_t)i * 128 + 2 * tid) = hi;
        *(uint2*)(yl + (size_t)i * 128 + 2 * tid) = lo;
    } else {
        out4[(size_t)i * 64 + tid] = y;
    }
}

// ---------------- launch ----------------------------------------------------
extern "C" void kernel_launch(void* const* d_in, const int* in_sizes, int n_in,
                              void* d_out, int out_size) {
    const float* x    = (const float*)d_in[0];
    const int*   ei   = (const int*)d_in[1];
    const float* W0   = (const float*)d_in[2];
    const float* as0  = (const float*)d_in[3];
    const float* ad0  = (const float*)d_in[4];
    const float* b0   = (const float*)d_in[5];
    const float* lnw0 = (const float*)d_in[6];
    const float* lnb0 = (const float*)d_in[7];
    const float* W1   = (const float*)d_in[8];
    const float* as1  = (const float*)d_in[9];
    const float* ad1  = (const float*)d_in[10];
    const float* b1   = (const float*)d_in[11];
    const float* lnw1 = (const float*)d_in[12];
    const float* lnb1 = (const float*)d_in[13];
    const float* W2   = (const float*)d_in[14];
    const float* as2  = (const float*)d_in[15];
    const float* ad2  = (const float*)d_in[16];
    const float* b2   = (const float*)d_in[17];
    const float* lnw2 = (const float*)d_in[18];
    const float* lnb2 = (const float*)d_in[19];
    float* out = (float*)d_out;

    int n = in_sizes[0] / 512;   // 50000
    int e = in_sizes[1] / 2;     // 800000
    const int* src = ei;
    const int* dst = ei + e;

    float *ph, *palpha, *pwexp;
    int *pcnt, *prow, *pcur, *pcol, *pcds;
    uint32_t *pxh, *pxl, *pyh, *pyl;
    uint32_t *pw0h, *pw0l, *pw1h, *pw1l, *pw2h, *pw2l;
    cudaGetSymbolAddress((void**)&ph, g_h);
    cudaGetSymbolAddress((void**)&palpha, g_alpha);
    cudaGetSymbolAddress((void**)&pwexp, g_wexp);
    cudaGetSymbolAddress((void**)&pcnt, g_cnt);
    cudaGetSymbolAddress((void**)&prow, g_rowptr);
    cudaGetSymbolAddress((void**)&pcur, g_cursor);
    cudaGetSymbolAddress((void**)&pcol, g_colsrc);
    cudaGetSymbolAddress((void**)&pcds, g_coldst);
    cudaGetSymbolAddress((void**)&pxh, g_xh);
    cudaGetSymbolAddress((void**)&pxl, g_xl);
    cudaGetSymbolAddress((void**)&pyh, g_yh);
    cudaGetSymbolAddress((void**)&pyl, g_yl);
    cudaGetSymbolAddress((void**)&pw0h, g_w0h);
    cudaGetSymbolAddress((void**)&pw0l, g_w0l);
    cudaGetSymbolAddress((void**)&pw1h, g_w1h);
    cudaGetSymbolAddress((void**)&pw1l, g_w1l);
    cudaGetSymbolAddress((void**)&pw2h, g_w2h);
    cudaGetSymbolAddress((void**)&pw2l, g_w2l);

    float* pas0 = palpha + (size_t)0 * MAXN * 4;
    float* pad0 = palpha + (size_t)1 * MAXN * 4;
    float* pas1 = palpha + (size_t)2 * MAXN * 4;
    float* pad1 = palpha + (size_t)3 * MAXN * 4;
    float* pas2 = palpha + (size_t)4 * MAXN * 4;
    float* pad2 = palpha + (size_t)5 * MAXN * 4;

    cudaFuncSetAttribute(gemm_bf16<4>, cudaFuncAttributeMaxDynamicSharedMemorySize, GSMEM);
    cudaFuncSetAttribute(gemm_bf16<1>, cudaFuncAttributeMaxDynamicSharedMemorySize, GSMEM);

    const int TPB = 256;
    const int egrid = (e + TPB - 1) / TPB;
    const int xtotal = n * 256;

    hist_kernel<<<egrid, TPB>>>(dst, pcnt, e, palpha, W0, W1, W2,
                                pw0h, pw0l, pw1h, pw1l, pw2h, pw2l,
                                (const float2*)x, pxh, pxl, xtotal);
    scan_kernel<<<1, 1024>>>(pcnt, prow, pcur, n);
    scatter_kernel<<<egrid, TPB>>>(src, dst, pcur, pcol, pcds, e);

    dim3 ggrid(NF / 128, (n + 127) / 128);

    // layer 0: GATConv(512 -> 4x64)
    gemm_bf16<4><<<ggrid, 256, GSMEM>>>(pxh, pxl, pw0h, pw0l, ph, n, 512,
                                        as0, ad0, pas0, pad0);
    weight_kernel<4><<<egrid, TPB>>>(pas0, pad0, pcol, pcds, pwexp, e);
    agg_kernel<4, true><<<n, 64>>>((const float4*)ph, pas0, pad0, prow, pcol, pwexp,
                                   (const float4*)b0, (const float4*)lnw0,
                                   (const float4*)lnb0, nullptr, pyh, pyl);

    // layer 1: GATConv(256 -> 4x64)
    gemm_bf16<4><<<ggrid, 256, GSMEM>>>(pyh, pyl, pw1h, pw1l, ph, n, 256,
                                        as1, ad1, pas1, pad1);
    weight_kernel<4><<<egrid, TPB>>>(pas1, pad1, pcol, pcds, pwexp, e);
    agg_kernel<4, true><<<n, 64>>>((const float4*)ph, pas1, pad1, prow, pcol, pwexp,
                                   (const float4*)b1, (const float4*)lnw1,
                                   (const float4*)lnb1, nullptr, pyh, pyl);

    // layer 2: GATConv(256 -> 1x256)
    gemm_bf16<1><<<ggrid, 256, GSMEM>>>(pyh, pyl, pw2h, pw2l, ph, n, 256,
                                        as2, ad2, pas2, pad2);
    weight_kernel<1><<<egrid, TPB>>>(pas2, pad2, pcol, pcds, pwexp, e);
    agg_kernel<1, false><<<n, 64>>>((const float4*)ph, pas2, pad2, prow, pcol, pwexp,
                                    (const float4*)b2, (const float4*)lnw2,
                                    (const float4*)lnb2, (float4*)out, nullptr, nullptr);
}

// round 15
// speedup vs baseline: 1.1660x; 1.0558x over previous
#include <cuda_runtime.h>
#include <cuda_bf16.h>
#include <stdint.h>
#include <math.h>

#define MAXN 50000
#define MAXE 800000
#define NF 256

// ---------------- scratch (device globals; no allocation allowed) ----------
__device__ float g_h[(size_t)MAXN * NF];     // GEMM fp32 output (for agg gather)
__device__ float g_alpha[(size_t)6 * MAXN * 4];
__device__ float g_wexp[(size_t)MAXE * 4];
__device__ int   g_cnt[MAXN];
__device__ int   g_rowptr[MAXN + 1];
__device__ int   g_cursor[MAXN];
__device__ int   g_colsrc[MAXE];
__device__ int   g_coldst[MAXE];
// pre-split activations: [row][kpair] packed bf16x2
__device__ uint32_t g_xh[(size_t)MAXN * 256], g_xl[(size_t)MAXN * 256];   // x: K=512
__device__ uint32_t g_yh[(size_t)MAXN * 128], g_yl[(size_t)MAXN * 128];   // layer outs
// pre-transposed, bf16-split weights: [n][kpair] packed bf16x2
__device__ uint32_t g_w0h[256 * 256], g_w0l[256 * 256];
__device__ uint32_t g_w1h[256 * 128], g_w1l[256 * 128];
__device__ uint32_t g_w2h[256 * 128], g_w2l[256 * 128];

// ---------------- bf16 split helpers ----------------------------------------
__device__ __forceinline__ uint32_t bf16_pack_hi(float f0, float f1) {
    __nv_bfloat16 h0 = __float2bfloat16(f0);
    __nv_bfloat16 h1 = __float2bfloat16(f1);
    return (uint32_t)__bfloat16_as_ushort(h0) | ((uint32_t)__bfloat16_as_ushort(h1) << 16);
}
__device__ __forceinline__ uint32_t bf16_pack_lo(float f0, float f1) {
    __nv_bfloat16 h0 = __float2bfloat16(f0);
    __nv_bfloat16 h1 = __float2bfloat16(f1);
    __nv_bfloat16 l0 = __float2bfloat16(f0 - __bfloat162float(h0));
    __nv_bfloat16 l1 = __float2bfloat16(f1 - __bfloat162float(h1));
    return (uint32_t)__bfloat16_as_ushort(l0) | ((uint32_t)__bfloat16_as_ushort(l1) << 16);
}

__device__ __forceinline__ void mma_bf16(float c[4],
                                         uint32_t a0, uint32_t a1, uint32_t a2, uint32_t a3,
                                         uint32_t b0, uint32_t b1) {
    asm volatile(
        "mma.sync.aligned.m16n8k16.row.col.f32.bf16.bf16.f32 "
        "{%0,%1,%2,%3}, {%4,%5,%6,%7}, {%8,%9}, {%0,%1,%2,%3};"
        : "+f"(c[0]), "+f"(c[1]), "+f"(c[2]), "+f"(c[3])
        : "r"(a0), "r"(a1), "r"(a2), "r"(a3), "r"(b0), "r"(b1));
}

__device__ __forceinline__ uint32_t smem_u32(const void* p) {
    uint32_t a;
    asm("{ .reg .u64 t; cvta.to.shared.u64 t, %1; cvt.u32.u64 %0, t; }" : "=r"(a) : "l"(p));
    return a;
}
__device__ __forceinline__ void cp16(uint32_t d, const uint32_t* s, bool p) {
    int sz = p ? 16 : 0;
    asm volatile("cp.async.cg.shared.global [%0], [%1], 16, %2;"
                 :: "r"(d), "l"(s), "r"(sz) : "memory");
}
#define CP_COMMIT() asm volatile("cp.async.commit_group;" ::: "memory")
#define CP_WAIT1()  asm volatile("cp.async.wait_group 1;" ::: "memory")

// ---------------- hist + alpha zero + weight prep + x split (fused) ---------
__global__ void hist_kernel(const int* __restrict__ dst, int* __restrict__ cnt, int e,
                            float* __restrict__ alpha,
                            const float* __restrict__ W0, const float* __restrict__ W1,
                            const float* __restrict__ W2,
                            uint32_t* __restrict__ w0h, uint32_t* __restrict__ w0l,
                            uint32_t* __restrict__ w1h, uint32_t* __restrict__ w1l,
                            uint32_t* __restrict__ w2h, uint32_t* __restrict__ w2l,
                            const float2* __restrict__ x2,
                            uint32_t* __restrict__ xh, uint32_t* __restrict__ xl,
                            int xtotal) {
    int t = blockIdx.x * blockDim.x + threadIdx.x;
    int nthr = gridDim.x * blockDim.x;
    if (t < e) atomicAdd(&cnt[dst[t]], 1);
    const int atot = 6 * MAXN * 4;
    for (int i = t; i < atot; i += nthr) alpha[i] = 0.f;
    const int T0 = 256 * 256, T1 = 256 * 128;
    if (t < T0) {
        int n = t >> 8, kp = t & 255;
        float f0 = W0[(2 * kp) * 256 + n];
        float f1 = W0[(2 * kp + 1) * 256 + n];
        w0h[n * 256 + kp] = bf16_pack_hi(f0, f1);
        w0l[n * 256 + kp] = bf16_pack_lo(f0, f1);
    } else if (t < T0 + T1) {
        int id = t - T0;
        int n = id >> 7, kp = id & 127;
        float f0 = W1[(2 * kp) * 256 + n];
        float f1 = W1[(2 * kp + 1) * 256 + n];
        w1h[n * 128 + kp] = bf16_pack_hi(f0, f1);
        w1l[n * 128 + kp] = bf16_pack_lo(f0, f1);
    } else if (t < T0 + 2 * T1) {
        int id = t - T0 - T1;
        int n = id >> 7, kp = id & 127;
        float f0 = W2[(2 * kp) * 256 + n];
        float f1 = W2[(2 * kp + 1) * 256 + n];
        w2h[n * 128 + kp] = bf16_pack_hi(f0, f1);
        w2l[n * 128 + kp] = bf16_pack_lo(f0, f1);
    }
    for (int i = t; i < xtotal; i += nthr) {
        float2 f = x2[i];
        xh[i] = bf16_pack_hi(f.x, f.y);
        xl[i] = bf16_pack_lo(f.x, f.y);
    }
}

__global__ void scan_kernel(int* __restrict__ cnt, int* __restrict__ rowptr,
                            int* __restrict__ cursor, int n) {
    __shared__ int sh[1024];
    int tid = threadIdx.x;
    int chunk = (n + 1023) >> 10;
    int base = tid * chunk;
    int s = 0;
    for (int j = 0; j < chunk; j++) {
        int idx = base + j;
        if (idx < n) s += cnt[idx];
    }
    sh[tid] = s;
    __syncthreads();
    for (int off = 1; off < 1024; off <<= 1) {
        int v = (tid >= off) ? sh[tid - off] : 0;
        __syncthreads();
        sh[tid] += v;
        __syncthreads();
    }
    int run = sh[tid] - s;
    for (int j = 0; j < chunk; j++) {
        int idx = base + j;
        if (idx < n) {
            rowptr[idx] = run;
            cursor[idx] = run;
            run += cnt[idx];
            cnt[idx] = 0;
        }
    }
    if (tid == 1023) rowptr[n] = run;
}

__global__ void scatter_kernel(const int* __restrict__ src, const int* __restrict__ dst,
                               int* __restrict__ cursor, int* __restrict__ colsrc,
                               int* __restrict__ coldst, int e) {
    int t = blockIdx.x * blockDim.x + threadIdx.x;
    if (t < e) {
        int d = dst[t];
        int p = atomicAdd(&cursor[d], 1);
        colsrc[p] = src[t];
        coldst[p] = d;
    }
}

// ---------------- per-edge softmax numerators --------------------------------
template <int H>
__global__ void weight_kernel(const float* __restrict__ asrc, const float* __restrict__ adst,
                              const int* __restrict__ colsrc, const int* __restrict__ coldst,
                              float* __restrict__ wexp, int e) {
    int t = blockIdx.x * blockDim.x + threadIdx.x;
    if (t < e) {
        int s = colsrc[t], d = coldst[t];
#pragma unroll
        for (int h = 0; h < H; h++) {
            float ev = asrc[s * H + h] + adst[d * H + h];
            ev = ev > 0.f ? ev : 0.2f * ev;
            wexp[t * H + h] = __expf(ev);
        }
    }
}

// ---------------- cp.async triple-buffered bf16x3 GEMM ----------------------
// C[M,256] = A[M,K] @ B[K,256]; operands pre-split in DRAM [major][kpair].
// CTA 128x128, 8 warps (2x4), warp tile 64x32, m16n8k16 bf16 mma, 3-term split.
// 3 super-slots x BK=32; per iter: wait_group 1 -> sync -> issue super p+2
// -> 96-mma burst. XOR swizzle (chunk ^= (row>>1)&3) on 16-word pitch keeps
// fragment LDS and cp.async stores conflict-free. Smem = 3 x 32KB = 96KB.
#define ARRW  2048                 // 128 rows x 16 words
#define SLOTW (4 * ARRW)
#define GSMEM (3 * SLOTW * 4)      // 98304 B

template <int H>
__global__ void __launch_bounds__(256, 2) gemm_bf16(
    const uint32_t* __restrict__ Ath, const uint32_t* __restrict__ Atl,
    const uint32_t* __restrict__ Bth, const uint32_t* __restrict__ Btl,
    float* __restrict__ C, int M, int K,
    const float* __restrict__ a_s, const float* __restrict__ a_d,
    float* __restrict__ asrc, float* __restrict__ adst)
{
    extern __shared__ uint32_t sm[];
    const uint32_t smb = smem_u32(sm);

    const int tid  = threadIdx.x;
    const int lane = tid & 31;
    const int w    = tid >> 5;
    const int g    = lane >> 2;
    const int t    = lane & 3;
    const int wm   = w >> 2;
    const int wn   = w & 3;

    const int row0 = blockIdx.y * 128;
    const int col0 = blockIdx.x * 128;
    const int KW   = K >> 1;           // kpairs per row
    const int NSUP = K >> 5;           // 32-K super-tiles

    // staging: thread -> (row r, half hh); copies chunks 2hh,2hh+1 per array
    const int r  = tid >> 1;
    const int hh = tid & 1;
    const int rq = (r >> 1) & 3;
    const bool aok = (row0 + r) < M;
    const int arow = aok ? (row0 + r) : (M - 1);
    const uint32_t* gAh = Ath + (size_t)arow * KW;
    const uint32_t* gAl = Atl + (size_t)arow * KW;
    const uint32_t* gBh = Bth + (size_t)(col0 + r) * KW;
    const uint32_t* gBl = Btl + (size_t)(col0 + r) * KW;
    // per-thread swizzled dst word offsets for its two chunks
    const int c0 = 2 * hh, c1 = 2 * hh + 1;
    const uint32_t d0 = smb + (uint32_t)(r * 16 + ((c0 ^ rq) << 2)) * 4;
    const uint32_t d1 = smb + (uint32_t)(r * 16 + ((c1 ^ rq) << 2)) * 4;

    float acc[4][4][4];
#pragma unroll
    for (int mt = 0; mt < 4; mt++)
#pragma unroll
        for (int nt = 0; nt < 4; nt++)
#pragma unroll
            for (int i = 0; i < 4; i++) acc[mt][nt][i] = 0.f;

    // prologue: issue supers 0 and 1 into slots 0, 1
#pragma unroll
    for (int s = 0; s < 2; s++) {
        uint32_t so = (uint32_t)(s * SLOTW) * 4;
        int kp0 = s * 16 + c0 * 4;
        int kp1 = s * 16 + c1 * 4;
        cp16(d0 + so,                gAh + kp0, aok);
        cp16(d1 + so,                gAh + kp1, aok);
        cp16(d0 + so + ARRW * 4,     gAl + kp0, aok);
        cp16(d1 + so + ARRW * 4,     gAl + kp1, aok);
        cp16(d0 + so + 2 * ARRW * 4, gBh + kp0, true);
        cp16(d1 + so + 2 * ARRW * 4, gBh + kp1, true);
        cp16(d0 + so + 3 * ARRW * 4, gBl + kp0, true);
        cp16(d1 + so + 3 * ARRW * 4, gBl + kp1, true);
        CP_COMMIT();
    }

    int slot = 0, nslot = 2;   // slot of super p; slot to fill with super p+2
    for (int p = 0; p < NSUP; p++) {
        CP_WAIT1();            // super p complete (p+1 may be in flight)
        __syncthreads();       // all warps done with slot nslot's old super

        int nx = p + 2;
        if (nx < NSUP) {
            uint32_t so = (uint32_t)(nslot * SLOTW) * 4;
            int kp0 = nx * 16 + c0 * 4;
            int kp1 = nx * 16 + c1 * 4;
            cp16(d0 + so,                gAh + kp0, aok);
            cp16(d1 + so,                gAh + kp1, aok);
            cp16(d0 + so + ARRW * 4,     gAl + kp0, aok);
            cp16(d1 + so + ARRW * 4,     gAl + kp1, aok);
            cp16(d0 + so + 2 * ARRW * 4, gBh + kp0, true);
            cp16(d1 + so + 2 * ARRW * 4, gBh + kp1, true);
            cp16(d0 + so + 3 * ARRW * 4, gBl + kp0, true);
            cp16(d1 + so + 3 * ARRW * 4, gBl + kp1, true);
        }
        CP_COMMIT();           // always commit (empty in tail)

        // ---- 96-mma burst on slot (term-major, dep dist = 4) ----
        const uint32_t* Ah = sm + slot * SLOTW;
        const uint32_t* Al = Ah + ARRW;
        const uint32_t* Bh = Ah + 2 * ARRW;
        const uint32_t* Bl = Ah + 3 * ARRW;
#pragma unroll
        for (int kk = 0; kk < 2; kk++) {
            uint32_t bh[4][2], bl[4][2];
#pragma unroll
            for (int nt = 0; nt < 4; nt++) {
                int n  = wn * 32 + nt * 8 + g;
                int nb = n * 16;
                int nq = (n >> 1) & 3;
                int o0 = ((2 * kk) ^ nq) << 2;
                int o1 = ((2 * kk + 1) ^ nq) << 2;
                bh[nt][0] = Bh[nb + o0 + t];
                bh[nt][1] = Bh[nb + o1 + t];
                bl[nt][0] = Bl[nb + o0 + t];
                bl[nt][1] = Bl[nb + o1 + t];
            }
#pragma unroll
            for (int mt = 0; mt < 4; mt++) {
                int rb = wm * 64 + mt * 16 + g;   // rb and rb+8 share (row>>1)&3
                int rq2 = (rb >> 1) & 3;
                int o0 = ((2 * kk) ^ rq2) << 2;
                int o1 = ((2 * kk + 1) ^ rq2) << 2;
                uint32_t ah[4], al[4];
                ah[0] = Ah[rb * 16 + o0 + t];
                ah[1] = Ah[(rb + 8) * 16 + o0 + t];
                ah[2] = Ah[rb * 16 + o1 + t];
                ah[3] = Ah[(rb + 8) * 16 + o1 + t];
                al[0] = Al[rb * 16 + o0 + t];
                al[1] = Al[(rb + 8) * 16 + o0 + t];
                al[2] = Al[rb * 16 + o1 + t];
                al[3] = Al[(rb + 8) * 16 + o1 + t];
#pragma unroll
                for (int nt = 0; nt < 4; nt++)
                    mma_bf16(acc[mt][nt], ah[0], ah[1], ah[2], ah[3], bh[nt][0], bh[nt][1]);
#pragma unroll
                for (int nt = 0; nt < 4; nt++)
                    mma_bf16(acc[mt][nt], ah[0], ah[1], ah[2], ah[3], bl[nt][0], bl[nt][1]);
#pragma unroll
                for (int nt = 0; nt < 4; nt++)
                    mma_bf16(acc[mt][nt], al[0], al[1], al[2], al[3], bh[nt][0], bh[nt][1]);
            }
        }
        slot = (slot == 2) ? 0 : slot + 1;
        nslot = (nslot == 2) ? 0 : nslot + 1;
    }

    // ---- epilogue 1: store C tile ----
#pragma unroll
    for (int mt = 0; mt < 4; mt++) {
        int r0 = row0 + wm * 64 + mt * 16 + g;
        int r1 = r0 + 8;
#pragma unroll
        for (int nt = 0; nt < 4; nt++) {
            int col = col0 + wn * 32 + nt * 8 + 2 * t;
            if (r0 < M)
                *(float2*)(C + (size_t)r0 * NF + col) = make_float2(acc[mt][nt][0], acc[mt][nt][1]);
            if (r1 < M)
                *(float2*)(C + (size_t)r1 * NF + col) = make_float2(acc[mt][nt][2], acc[mt][nt][3]);
        }
    }

    // ---- epilogue 2: fused alpha projection (atomic; zeroed by hist) -------
    {
        float asv[4][2], adv[4][2];
#pragma unroll
        for (int nt = 0; nt < 4; nt++)
#pragma unroll
            for (int i = 0; i < 2; i++) {
                int gcol = col0 + wn * 32 + nt * 8 + 2 * t + i;
                asv[nt][i] = a_s[gcol];
                adv[nt][i] = a_d[gcol];
            }
        const int hd = (H == 4) ? ((col0 + wn * 32) >> 6) : 0;
#pragma unroll
        for (int mt = 0; mt < 4; mt++) {
            float sa0 = 0.f, sd0 = 0.f, sa1 = 0.f, sd1 = 0.f;
#pragma unroll
            for (int nt = 0; nt < 4; nt++)
#pragma unroll
                for (int i = 0; i < 2; i++) {
                    sa0 += acc[mt][nt][i]     * asv[nt][i];
                    sd0 += acc[mt][nt][i]     * adv[nt][i];
                    sa1 += acc[mt][nt][2 + i] * asv[nt][i];
                    sd1 += acc[mt][nt][2 + i] * adv[nt][i];
                }
#pragma unroll
            for (int o = 1; o <= 2; o <<= 1) {
                sa0 += __shfl_xor_sync(0xffffffffu, sa0, o);
                sd0 += __shfl_xor_sync(0xffffffffu, sd0, o);
                sa1 += __shfl_xor_sync(0xffffffffu, sa1, o);
                sd1 += __shfl_xor_sync(0xffffffffu, sd1, o);
            }
            if (t == 0) {
                int r0 = row0 + wm * 64 + mt * 16 + g;
                int r1 = r0 + 8;
                if (r0 < M) {
                    atomicAdd(&asrc[r0 * H + hd], sa0);
                    atomicAdd(&adst[r0 * H + hd], sd0);
                }
                if (r1 < M) {
                    atomicAdd(&asrc[r1 * H + hd], sa1);
                    atomicAdd(&adst[r1 * H + hd], sd1);
                }
            }
        }
    }
}

// ---------------- block-sum helper (64 threads, 2 warps) ---------------------
__device__ __forceinline__ float block_sum64(float v, float* red) {
#pragma unroll
    for (int o = 16; o > 0; o >>= 1) v += __shfl_xor_sync(0xffffffffu, v, o);
    int wid = threadIdx.x >> 5;
    if ((threadIdx.x & 31) == 0) red[wid] = v;
    __syncthreads();
    float s = red[0] + red[1];
    __syncthreads();
    return s;
}

// ---------------- fused aggregation + bias + LN + ELU -----------------------
template <int H, bool SPLIT>
__global__ void __launch_bounds__(64) agg_kernel(
    const float4* __restrict__ hfeat4,
    const float* __restrict__ asrc, const float* __restrict__ adst,
    const int* __restrict__ rowptr, const int* __restrict__ colsrc,
    const float* __restrict__ wexp,
    const float4* __restrict__ bias4, const float4* __restrict__ lnw4,
    const float4* __restrict__ lnb4,
    float4* __restrict__ out4,
    uint32_t* __restrict__ yh, uint32_t* __restrict__ yl)
{
    __shared__ float red[2];

    int i   = blockIdx.x;
    int tid = threadIdx.x;
    int head = (H == 4) ? (tid >> 4) : 0;

    float e0 = asrc[i * H + head] + adst[i * H + head];
    e0 = e0 > 0.f ? e0 : 0.2f * e0;
    float w0 = __expf(e0);
    float den = w0;
    float4 hv = hfeat4[(size_t)i * 64 + tid];
    float4 acc = make_float4(w0 * hv.x, w0 * hv.y, w0 * hv.z, w0 * hv.w);

    int beg = rowptr[i], end = rowptr[i + 1];
    int p = beg;
    for (; p + 4 <= end; p += 4) {
        int s0 = colsrc[p], s1 = colsrc[p + 1], s2 = colsrc[p + 2], s3 = colsrc[p + 3];
        float w_0 = wexp[(p + 0) * H + head];
        float w_1 = wexp[(p + 1) * H + head];
        float w_2 = wexp[(p + 2) * H + head];
        float w_3 = wexp[(p + 3) * H + head];
        float4 h0 = hfeat4[(size_t)s0 * 64 + tid];
        float4 h1 = hfeat4[(size_t)s1 * 64 + tid];
        float4 h2 = hfeat4[(size_t)s2 * 64 + tid];
        float4 h3 = hfeat4[(size_t)s3 * 64 + tid];
        den += (w_0 + w_1) + (w_2 + w_3);
        acc.x += w_0 * h0.x + w_1 * h1.x + w_2 * h2.x + w_3 * h3.x;
        acc.y += w_0 * h0.y + w_1 * h1.y + w_2 * h2.y + w_3 * h3.y;
        acc.z += w_0 * h0.z + w_1 * h1.z + w_2 * h2.z + w_3 * h3.z;
        acc.w += w_0 * h0.w + w_1 * h1.w + w_2 * h2.w + w_3 * h3.w;
    }
    for (; p < end; p++) {
        int s0 = colsrc[p];
        float wv = wexp[p * H + head];
        float4 h0 = hfeat4[(size_t)s0 * 64 + tid];
        den += wv;
        acc.x += wv * h0.x; acc.y += wv * h0.y; acc.z += wv * h0.z; acc.w += wv * h0.w;
    }

    float4 bv = bias4[tid];
    float inv = 1.f / den;
    float4 v = make_float4(acc.x * inv + bv.x, acc.y * inv + bv.y,
                           acc.z * inv + bv.z, acc.w * inv + bv.w);

    float mean = block_sum64(v.x + v.y + v.z + v.w, red) * (1.f / NF);
    float4 dl = make_float4(v.x - mean, v.y - mean, v.z - mean, v.w - mean);
    float var = block_sum64(dl.x * dl.x + dl.y * dl.y + dl.z * dl.z + dl.w * dl.w, red)
                * (1.f / NF);
    float rs = rsqrtf(var + 1e-5f);
    float4 wv4 = lnw4[tid];
    float4 bb = lnb4[tid];
    float4 y;
    y.x = dl.x * rs * wv4.x + bb.x;
    y.y = dl.y * rs * wv4.y + bb.y;
    y.z = dl.z * rs * wv4.z + bb.z;
    y.w = dl.w * rs * wv4.w + bb.w;
    y.x = y.x > 0.f ? y.x : expm1f(y.x);
    y.y = y.y > 0.f ? y.y : expm1f(y.y);
    y.z = y.z > 0.f ? y.z : expm1f(y.z);
    y.w = y.w > 0.f ? y.w : expm1f(y.w);

    if (SPLIT) {
        uint2 hi, lo;
        hi.x = bf16_pack_hi(y.x, y.y);
        hi.y = bf16_pack_hi(y.z, y.w);
        lo.x = bf16_pack_lo(y.x, y.y);
        lo.y = bf16_pack_lo(y.z, y.w);
        *(uint2*)(yh + (size_t)i * 128 + 2 * tid) = hi;
        *(uint2*)(yl + (size_t)i * 128 + 2 * tid) = lo;
    } else {
        out4[(size_t)i * 64 + tid] = y;
    }
}

// ---------------- launch ----------------------------------------------------
extern "C" void kernel_launch(void* const* d_in, const int* in_sizes, int n_in,
                              void* d_out, int out_size) {
    const float* x    = (const float*)d_in[0];
    const int*   ei   = (const int*)d_in[1];
    const float* W0   = (const float*)d_in[2];
    const float* as0  = (const float*)d_in[3];
    const float* ad0  = (const float*)d_in[4];
    const float* b0   = (const float*)d_in[5];
    const float* lnw0 = (const float*)d_in[6];
    const float* lnb0 = (const float*)d_in[7];
    const float* W1   = (const float*)d_in[8];
    const float* as1  = (const float*)d_in[9];
    const float* ad1  = (const float*)d_in[10];
    const float* b1   = (const float*)d_in[11];
    const float* lnw1 = (const float*)d_in[12];
    const float* lnb1 = (const float*)d_in[13];
    const float* W2   = (const float*)d_in[14];
    const float* as2  = (const float*)d_in[15];
    const float* ad2  = (const float*)d_in[16];
    const float* b2   = (const float*)d_in[17];
    const float* lnw2 = (const float*)d_in[18];
    const float* lnb2 = (const float*)d_in[19];
    float* out = (float*)d_out;

    int n = in_sizes[0] / 512;   // 50000
    int e = in_sizes[1] / 2;     // 800000
    const int* src = ei;
    const int* dst = ei + e;

    float *ph, *palpha, *pwexp;
    int *pcnt, *prow, *pcur, *pcol, *pcds;
    uint32_t *pxh, *pxl, *pyh, *pyl;
    uint32_t *pw0h, *pw0l, *pw1h, *pw1l, *pw2h, *pw2l;
    cudaGetSymbolAddress((void**)&ph, g_h);
    cudaGetSymbolAddress((void**)&palpha, g_alpha);
    cudaGetSymbolAddress((void**)&pwexp, g_wexp);
    cudaGetSymbolAddress((void**)&pcnt, g_cnt);
    cudaGetSymbolAddress((void**)&prow, g_rowptr);
    cudaGetSymbolAddress((void**)&pcur, g_cursor);
    cudaGetSymbolAddress((void**)&pcol, g_colsrc);
    cudaGetSymbolAddress((void**)&pcds, g_coldst);
    cudaGetSymbolAddress((void**)&pxh, g_xh);
    cudaGetSymbolAddress((void**)&pxl, g_xl);
    cudaGetSymbolAddress((void**)&pyh, g_yh);
    cudaGetSymbolAddress((void**)&pyl, g_yl);
    cudaGetSymbolAddress((void**)&pw0h, g_w0h);
    cudaGetSymbolAddress((void**)&pw0l, g_w0l);
    cudaGetSymbolAddress((void**)&pw1h, g_w1h);
    cudaGetSymbolAddress((void**)&pw1l, g_w1l);
    cudaGetSymbolAddress((void**)&pw2h, g_w2h);
    cudaGetSymbolAddress((void**)&pw2l, g_w2l);

    float* pas0 = palpha + (size_t)0 * MAXN * 4;
    float* pad0 = palpha + (size_t)1 * MAXN * 4;
    float* pas1 = palpha + (size_t)2 * MAXN * 4;
    float* pad1 = palpha + (size_t)3 * MAXN * 4;
    float* pas2 = palpha + (size_t)4 * MAXN * 4;
    float* pad2 = palpha + (size_t)5 * MAXN * 4;

    cudaFuncSetAttribute(gemm_bf16<4>, cudaFuncAttributeMaxDynamicSharedMemorySize, GSMEM);
    cudaFuncSetAttribute(gemm_bf16<1>, cudaFuncAttributeMaxDynamicSharedMemorySize, GSMEM);

    const int TPB = 256;
    const int egrid = (e + TPB - 1) / TPB;
    const int xtotal = n * 256;

    hist_kernel<<<egrid, TPB>>>(dst, pcnt, e, palpha, W0, W1, W2,
                                pw0h, pw0l, pw1h, pw1l, pw2h, pw2l,
                                (const float2*)x, pxh, pxl, xtotal);
    scan_kernel<<<1, 1024>>>(pcnt, prow, pcur, n);
    scatter_kernel<<<egrid, TPB>>>(src, dst, pcur, pcol, pcds, e);

    dim3 ggrid(NF / 128, (n + 127) / 128);

    // layer 0: GATConv(512 -> 4x64)
    gemm_bf16<4><<<ggrid, 256, GSMEM>>>(pxh, pxl, pw0h, pw0l, ph, n, 512,
                                        as0, ad0, pas0, pad0);
    weight_kernel<4><<<egrid, TPB>>>(pas0, pad0, pcol, pcds, pwexp, e);
    agg_kernel<4, true><<<n, 64>>>((const float4*)ph, pas0, pad0, prow, pcol, pwexp,
                                   (const float4*)b0, (const float4*)lnw0,
                                   (const float4*)lnb0, nullptr, pyh, pyl);

    // layer 1: GATConv(256 -> 4x64)
    gemm_bf16<4><<<ggrid, 256, GSMEM>>>(pyh, pyl, pw1h, pw1l, ph, n, 256,
                                        as1, ad1, pas1, pad1);
    weight_kernel<4><<<egrid, TPB>>>(pas1, pad1, pcol, pcds, pwexp, e);
    agg_kernel<4, true><<<n, 64>>>((const float4*)ph, pas1, pad1, prow, pcol, pwexp,
                                   (const float4*)b1, (const float4*)lnw1,
                                   (const float4*)lnb1, nullptr, pyh, pyl);

    // layer 2: GATConv(256 -> 1x256)
    gemm_bf16<1><<<ggrid, 256, GSMEM>>>(pyh, pyl, pw2h, pw2l, ph, n, 256,
                                        as2, ad2, pas2, pad2);
    weight_kernel<1><<<egrid, TPB>>>(pas2, pad2, pcol, pcds, pwexp, e);
    agg_kernel<1, false><<<n, 64>>>((const float4*)ph, pas2, pad2, prow, pcol, pwexp,
                                    (const float4*)b2, (const float4*)lnw2,
                                    (const float4*)lnb2, (float4*)out, nullptr, nullptr);
}

// round 16
// speedup vs baseline: 1.2168x; 1.0435x over previous
#include <cuda_runtime.h>
#include <cuda_bf16.h>
#include <stdint.h>
#include <math.h>

#define MAXN 50000
#define MAXE 800000
#define NF 256

// ---------------- scratch (device globals; no allocation allowed) ----------
__device__ float g_h[(size_t)MAXN * NF];     // GEMM fp32 output (for agg gather)
__device__ float g_alpha[(size_t)6 * MAXN * 4];
__device__ float g_wexp[(size_t)MAXE * 4];
__device__ int   g_cnt[MAXN];
__device__ int   g_rowptr[MAXN + 1];
__device__ int   g_cursor[MAXN];
__device__ int   g_colsrc[MAXE];
__device__ int   g_coldst[MAXE];
// pre-split activations: [row][kpair] packed bf16x2
__device__ uint32_t g_xh[(size_t)MAXN * 256], g_xl[(size_t)MAXN * 256];   // x: K=512
__device__ uint32_t g_yh[(size_t)MAXN * 128], g_yl[(size_t)MAXN * 128];   // layer outs
// pre-transposed, bf16-split weights: [n][kpair] packed bf16x2
__device__ uint32_t g_w0h[256 * 256], g_w0l[256 * 256];
__device__ uint32_t g_w1h[256 * 128], g_w1l[256 * 128];
__device__ uint32_t g_w2h[256 * 128], g_w2l[256 * 128];

// ---------------- bf16 split helpers ----------------------------------------
__device__ __forceinline__ uint32_t bf16_pack_hi(float f0, float f1) {
    __nv_bfloat16 h0 = __float2bfloat16(f0);
    __nv_bfloat16 h1 = __float2bfloat16(f1);
    return (uint32_t)__bfloat16_as_ushort(h0) | ((uint32_t)__bfloat16_as_ushort(h1) << 16);
}
__device__ __forceinline__ uint32_t bf16_pack_lo(float f0, float f1) {
    __nv_bfloat16 h0 = __float2bfloat16(f0);
    __nv_bfloat16 h1 = __float2bfloat16(f1);
    __nv_bfloat16 l0 = __float2bfloat16(f0 - __bfloat162float(h0));
    __nv_bfloat16 l1 = __float2bfloat16(f1 - __bfloat162float(h1));
    return (uint32_t)__bfloat16_as_ushort(l0) | ((uint32_t)__bfloat16_as_ushort(l1) << 16);
}

__device__ __forceinline__ void mma_bf16(float c[4],
                                         uint32_t a0, uint32_t a1, uint32_t a2, uint32_t a3,
                                         uint32_t b0, uint32_t b1) {
    asm volatile(
        "mma.sync.aligned.m16n8k16.row.col.f32.bf16.bf16.f32 "
        "{%0,%1,%2,%3}, {%4,%5,%6,%7}, {%8,%9}, {%0,%1,%2,%3};"
        : "+f"(c[0]), "+f"(c[1]), "+f"(c[2]), "+f"(c[3])
        : "r"(a0), "r"(a1), "r"(a2), "r"(a3), "r"(b0), "r"(b1));
}

__device__ __forceinline__ uint32_t smem_u32(const void* p) {
    uint32_t a;
    asm("{ .reg .u64 t; cvta.to.shared.u64 t, %1; cvt.u32.u64 %0, t; }" : "=r"(a) : "l"(p));
    return a;
}
__device__ __forceinline__ void cp16(uint32_t d, const uint32_t* s, bool p) {
    int sz = p ? 16 : 0;
    asm volatile("cp.async.cg.shared.global [%0], [%1], 16, %2;"
                 :: "r"(d), "l"(s), "r"(sz) : "memory");
}
#define CP_COMMIT() asm volatile("cp.async.commit_group;" ::: "memory")
#define CP_WAIT1()  asm volatile("cp.async.wait_group 1;" ::: "memory")

__device__ __forceinline__ void ldsm4(uint32_t a, uint32_t& r0, uint32_t& r1,
                                      uint32_t& r2, uint32_t& r3) {
    asm volatile("ldmatrix.sync.aligned.m8n8.x4.shared.b16 {%0,%1,%2,%3}, [%4];"
                 : "=r"(r0), "=r"(r1), "=r"(r2), "=r"(r3) : "r"(a));
}

// ---------------- hist + alpha zero + weight prep + x split (fused) ---------
__global__ void hist_kernel(const int* __restrict__ dst, int* __restrict__ cnt, int e,
                            float* __restrict__ alpha,
                            const float* __restrict__ W0, const float* __restrict__ W1,
                            const float* __restrict__ W2,
                            uint32_t* __restrict__ w0h, uint32_t* __restrict__ w0l,
                            uint32_t* __restrict__ w1h, uint32_t* __restrict__ w1l,
                            uint32_t* __restrict__ w2h, uint32_t* __restrict__ w2l,
                            const float2* __restrict__ x2,
                            uint32_t* __restrict__ xh, uint32_t* __restrict__ xl,
                            int xtotal) {
    int t = blockIdx.x * blockDim.x + threadIdx.x;
    int nthr = gridDim.x * blockDim.x;
    if (t < e) atomicAdd(&cnt[dst[t]], 1);
    const int atot = 6 * MAXN * 4;
    for (int i = t; i < atot; i += nthr) alpha[i] = 0.f;
    const int T0 = 256 * 256, T1 = 256 * 128;
    if (t < T0) {
        int n = t >> 8, kp = t & 255;
        float f0 = W0[(2 * kp) * 256 + n];
        float f1 = W0[(2 * kp + 1) * 256 + n];
        w0h[n * 256 + kp] = bf16_pack_hi(f0, f1);
        w0l[n * 256 + kp] = bf16_pack_lo(f0, f1);
    } else if (t < T0 + T1) {
        int id = t - T0;
        int n = id >> 7, kp = id & 127;
        float f0 = W1[(2 * kp) * 256 + n];
        float f1 = W1[(2 * kp + 1) * 256 + n];
        w1h[n * 128 + kp] = bf16_pack_hi(f0, f1);
        w1l[n * 128 + kp] = bf16_pack_lo(f0, f1);
    } else if (t < T0 + 2 * T1) {
        int id = t - T0 - T1;
        int n = id >> 7, kp = id & 127;
        float f0 = W2[(2 * kp) * 256 + n];
        float f1 = W2[(2 * kp + 1) * 256 + n];
        w2h[n * 128 + kp] = bf16_pack_hi(f0, f1);
        w2l[n * 128 + kp] = bf16_pack_lo(f0, f1);
    }
    for (int i = t; i < xtotal; i += nthr) {
        float2 f = x2[i];
        xh[i] = bf16_pack_hi(f.x, f.y);
        xl[i] = bf16_pack_lo(f.x, f.y);
    }
}

__global__ void scan_kernel(int* __restrict__ cnt, int* __restrict__ rowptr,
                            int* __restrict__ cursor, int n) {
    __shared__ int sh[1024];
    int tid = threadIdx.x;
    int chunk = (n + 1023) >> 10;
    int base = tid * chunk;
    int s = 0;
    for (int j = 0; j < chunk; j++) {
        int idx = base + j;
        if (idx < n) s += cnt[idx];
    }
    sh[tid] = s;
    __syncthreads();
    for (int off = 1; off < 1024; off <<= 1) {
        int v = (tid >= off) ? sh[tid - off] : 0;
        __syncthreads();
        sh[tid] += v;
        __syncthreads();
    }
    int run = sh[tid] - s;
    for (int j = 0; j < chunk; j++) {
        int idx = base + j;
        if (idx < n) {
            rowptr[idx] = run;
            cursor[idx] = run;
            run += cnt[idx];
            cnt[idx] = 0;
        }
    }
    if (tid == 1023) rowptr[n] = run;
}

__global__ void scatter_kernel(const int* __restrict__ src, const int* __restrict__ dst,
                               int* __restrict__ cursor, int* __restrict__ colsrc,
                               int* __restrict__ coldst, int e) {
    int t = blockIdx.x * blockDim.x + threadIdx.x;
    if (t < e) {
        int d = dst[t];
        int p = atomicAdd(&cursor[d], 1);
        colsrc[p] = src[t];
        coldst[p] = d;
    }
}

// ---------------- per-edge softmax numerators --------------------------------
template <int H>
__global__ void weight_kernel(const float* __restrict__ asrc, const float* __restrict__ adst,
                              const int* __restrict__ colsrc, const int* __restrict__ coldst,
                              float* __restrict__ wexp, int e) {
    int t = blockIdx.x * blockDim.x + threadIdx.x;
    if (t < e) {
        int s = colsrc[t], d = coldst[t];
#pragma unroll
        for (int h = 0; h < H; h++) {
            float ev = asrc[s * H + h] + adst[d * H + h];
            ev = ev > 0.f ? ev : 0.2f * ev;
            wexp[t * H + h] = __expf(ev);
        }
    }
}

// ---------------- cp.async triple-buffered bf16x3 GEMM (ldmatrix frags) -----
// C[M,256] = A[M,K] @ B[K,256]; operands pre-split in DRAM [major][kpair].
// CTA 128x128, 8 warps (2x4), warp tile 64x32, m16n8k16 bf16 mma, 3-term split.
// 3 super-slots x BK=32; per iter: wait_group 1 -> sync -> issue super p+2
// -> 96-mma burst. XOR swizzle (chunk ^= (row>>1)&3) on 16-word pitch.
// Fragments loaded with ldmatrix.x4 (12 LDSM/kk vs 48 scalar LDS).
#define ARRW  2048                 // 128 rows x 16 words
#define SLOTW (4 * ARRW)
#define GSMEM (3 * SLOTW * 4)      // 98304 B

template <int H>
__global__ void __launch_bounds__(256, 2) gemm_bf16(
    const uint32_t* __restrict__ Ath, const uint32_t* __restrict__ Atl,
    const uint32_t* __restrict__ Bth, const uint32_t* __restrict__ Btl,
    float* __restrict__ C, int M, int K,
    const float* __restrict__ a_s, const float* __restrict__ a_d,
    float* __restrict__ asrc, float* __restrict__ adst)
{
    extern __shared__ uint32_t sm[];
    const uint32_t smb = smem_u32(sm);

    const int tid  = threadIdx.x;
    const int lane = tid & 31;
    const int w    = tid >> 5;
    const int g    = lane >> 2;
    const int t    = lane & 3;
    const int wm   = w >> 2;
    const int wn   = w & 3;

    const int row0 = blockIdx.y * 128;
    const int col0 = blockIdx.x * 128;
    const int KW   = K >> 1;           // kpairs per row
    const int NSUP = K >> 5;           // 32-K super-tiles

    // staging: thread -> (row r, half hh); copies chunks 2hh,2hh+1 per array
    const int r  = tid >> 1;
    const int hh = tid & 1;
    const int rq = (r >> 1) & 3;
    const bool aok = (row0 + r) < M;
    const int arow = aok ? (row0 + r) : (M - 1);
    const uint32_t* gAh = Ath + (size_t)arow * KW;
    const uint32_t* gAl = Atl + (size_t)arow * KW;
    const uint32_t* gBh = Bth + (size_t)(col0 + r) * KW;
    const uint32_t* gBl = Btl + (size_t)(col0 + r) * KW;
    const int c0 = 2 * hh, c1 = 2 * hh + 1;
    const uint32_t d0 = smb + (uint32_t)(r * 16 + ((c0 ^ rq) << 2)) * 4;
    const uint32_t d1 = smb + (uint32_t)(r * 16 + ((c1 ^ rq) << 2)) * 4;

    // ldmatrix lane decomposition
    const int lrowA  = lane & 15;       // A tile row within 16
    const int lhalfA = lane >> 4;       // A chunk selector (k half)
    const int lrowB  = lane & 7;        // B tile row within 8
    const int lselB  = (lane >> 3) & 1; // B chunk selector
    const int lntB   = lane >> 4;       // B nt offset within pair

    float acc[4][4][4];
#pragma unroll
    for (int mt = 0; mt < 4; mt++)
#pragma unroll
        for (int nt = 0; nt < 4; nt++)
#pragma unroll
            for (int i = 0; i < 4; i++) acc[mt][nt][i] = 0.f;

    // prologue: issue supers 0 and 1 into slots 0, 1
#pragma unroll
    for (int s = 0; s < 2; s++) {
        uint32_t so = (uint32_t)(s * SLOTW) * 4;
        int kp0 = s * 16 + c0 * 4;
        int kp1 = s * 16 + c1 * 4;
        cp16(d0 + so,                gAh + kp0, aok);
        cp16(d1 + so,                gAh + kp1, aok);
        cp16(d0 + so + ARRW * 4,     gAl + kp0, aok);
        cp16(d1 + so + ARRW * 4,     gAl + kp1, aok);
        cp16(d0 + so + 2 * ARRW * 4, gBh + kp0, true);
        cp16(d1 + so + 2 * ARRW * 4, gBh + kp1, true);
        cp16(d0 + so + 3 * ARRW * 4, gBl + kp0, true);
        cp16(d1 + so + 3 * ARRW * 4, gBl + kp1, true);
        CP_COMMIT();
    }

    int slot = 0, nslot = 2;
    for (int p = 0; p < NSUP; p++) {
        CP_WAIT1();
        __syncthreads();

        int nx = p + 2;
        if (nx < NSUP) {
            uint32_t so = (uint32_t)(nslot * SLOTW) * 4;
            int kp0 = nx * 16 + c0 * 4;
            int kp1 = nx * 16 + c1 * 4;
            cp16(d0 + so,                gAh + kp0, aok);
            cp16(d1 + so,                gAh + kp1, aok);
            cp16(d0 + so + ARRW * 4,     gAl + kp0, aok);
            cp16(d1 + so + ARRW * 4,     gAl + kp1, aok);
            cp16(d0 + so + 2 * ARRW * 4, gBh + kp0, true);
            cp16(d1 + so + 2 * ARRW * 4, gBh + kp1, true);
            cp16(d0 + so + 3 * ARRW * 4, gBl + kp0, true);
            cp16(d1 + so + 3 * ARRW * 4, gBl + kp1, true);
        }
        CP_COMMIT();

        // ---- 96-mma burst on slot (ldmatrix frags, term-major) ----
        const uint32_t sb_slot = smb + (uint32_t)(slot * SLOTW) * 4;
        const uint32_t baseAh = sb_slot;
        const uint32_t baseAl = sb_slot + ARRW * 4;
        const uint32_t baseBh = sb_slot + 2 * ARRW * 4;
        const uint32_t baseBl = sb_slot + 3 * ARRW * 4;
#pragma unroll
        for (int kk = 0; kk < 2; kk++) {
            uint32_t bh[4][2], bl[4][2];
#pragma unroll
            for (int j = 0; j < 4; j += 2) {
                int n = wn * 32 + (j + lntB) * 8 + lrowB;
                int c = 2 * kk + lselB;
                int q = (n >> 1) & 3;
                uint32_t off = (uint32_t)(n * 16 + ((c ^ q) << 2)) * 4;
                ldsm4(baseBh + off, bh[j][0], bh[j][1], bh[j + 1][0], bh[j + 1][1]);
                ldsm4(baseBl + off, bl[j][0], bl[j][1], bl[j + 1][0], bl[j + 1][1]);
            }
#pragma unroll
            for (int mt = 0; mt < 4; mt++) {
                int rowA = wm * 64 + mt * 16 + lrowA;
                int cA = 2 * kk + lhalfA;
                int qA = (rowA >> 1) & 3;
                uint32_t offA = (uint32_t)(rowA * 16 + ((cA ^ qA) << 2)) * 4;
                uint32_t ah[4], al[4];
                ldsm4(baseAh + offA, ah[0], ah[1], ah[2], ah[3]);
                ldsm4(baseAl + offA, al[0], al[1], al[2], al[3]);
#pragma unroll
                for (int nt = 0; nt < 4; nt++)
                    mma_bf16(acc[mt][nt], ah[0], ah[1], ah[2], ah[3], bh[nt][0], bh[nt][1]);
#pragma unroll
                for (int nt = 0; nt < 4; nt++)
                    mma_bf16(acc[mt][nt], ah[0], ah[1], ah[2], ah[3], bl[nt][0], bl[nt][1]);
#pragma unroll
                for (int nt = 0; nt < 4; nt++)
                    mma_bf16(acc[mt][nt], al[0], al[1], al[2], al[3], bh[nt][0], bh[nt][1]);
            }
        }
        slot = (slot == 2) ? 0 : slot + 1;
        nslot = (nslot == 2) ? 0 : nslot + 1;
    }

    // ---- epilogue 1: store C tile ----
#pragma unroll
    for (int mt = 0; mt < 4; mt++) {
        int r0 = row0 + wm * 64 + mt * 16 + g;
        int r1 = r0 + 8;
#pragma unroll
        for (int nt = 0; nt < 4; nt++) {
            int col = col0 + wn * 32 + nt * 8 + 2 * t;
            if (r0 < M)
                *(float2*)(C + (size_t)r0 * NF + col) = make_float2(acc[mt][nt][0], acc[mt][nt][1]);
            if (r1 < M)
                *(float2*)(C + (size_t)r1 * NF + col) = make_float2(acc[mt][nt][2], acc[mt][nt][3]);
        }
    }

    // ---- epilogue 2: fused alpha projection (atomic; zeroed by hist) -------
    {
        float asv[4][2], adv[4][2];
#pragma unroll
        for (int nt = 0; nt < 4; nt++)
#pragma unroll
            for (int i = 0; i < 2; i++) {
                int gcol = col0 + wn * 32 + nt * 8 + 2 * t + i;
                asv[nt][i] = a_s[gcol];
                adv[nt][i] = a_d[gcol];
            }
        const int hd = (H == 4) ? ((col0 + wn * 32) >> 6) : 0;
#pragma unroll
        for (int mt = 0; mt < 4; mt++) {
            float sa0 = 0.f, sd0 = 0.f, sa1 = 0.f, sd1 = 0.f;
#pragma unroll
            for (int nt = 0; nt < 4; nt++)
#pragma unroll
                for (int i = 0; i < 2; i++) {
                    sa0 += acc[mt][nt][i]     * asv[nt][i];
                    sd0 += acc[mt][nt][i]     * adv[nt][i];
                    sa1 += acc[mt][nt][2 + i] * asv[nt][i];
                    sd1 += acc[mt][nt][2 + i] * adv[nt][i];
                }
#pragma unroll
            for (int o = 1; o <= 2; o <<= 1) {
                sa0 += __shfl_xor_sync(0xffffffffu, sa0, o);
                sd0 += __shfl_xor_sync(0xffffffffu, sd0, o);
                sa1 += __shfl_xor_sync(0xffffffffu, sa1, o);
                sd1 += __shfl_xor_sync(0xffffffffu, sd1, o);
            }
            if (t == 0) {
                int r0 = row0 + wm * 64 + mt * 16 + g;
                int r1 = r0 + 8;
                if (r0 < M) {
                    atomicAdd(&asrc[r0 * H + hd], sa0);
                    atomicAdd(&adst[r0 * H + hd], sd0);
                }
                if (r1 < M) {
                    atomicAdd(&asrc[r1 * H + hd], sa1);
                    atomicAdd(&adst[r1 * H + hd], sd1);
                }
            }
        }
    }
}

// ---------------- block-sum helper (64 threads, 2 warps) ---------------------
__device__ __forceinline__ float block_sum64(float v, float* red) {
#pragma unroll
    for (int o = 16; o > 0; o >>= 1) v += __shfl_xor_sync(0xffffffffu, v, o);
    int wid = threadIdx.x >> 5;
    if ((threadIdx.x & 31) == 0) red[wid] = v;
    __syncthreads();
    float s = red[0] + red[1];
    __syncthreads();
    return s;
}

// ---------------- fused aggregation + bias + LN + ELU -----------------------
template <int H, bool SPLIT>
__global__ void __launch_bounds__(64) agg_kernel(
    const float4* __restrict__ hfeat4,
    const float* __restrict__ asrc, const float* __restrict__ adst,
    const int* __restrict__ rowptr, const int* __restrict__ colsrc,
    const float* __restrict__ wexp,
    const float4* __restrict__ bias4, const float4* __restrict__ lnw4,
    const float4* __restrict__ lnb4,
    float4* __restrict__ out4,
    uint32_t* __restrict__ yh, uint32_t* __restrict__ yl)
{
    __shared__ float red[2];

    int i   = blockIdx.x;
    int tid = threadIdx.x;
    int head = (H == 4) ? (tid >> 4) : 0;

    float e0 = asrc[i * H + head] + adst[i * H + head];
    e0 = e0 > 0.f ? e0 : 0.2f * e0;
    float w0 = __expf(e0);
    float den = w0;
    float4 hv = hfeat4[(size_t)i * 64 + tid];
    float4 acc = make_float4(w0 * hv.x, w0 * hv.y, w0 * hv.z, w0 * hv.w);

    int beg = rowptr[i], end = rowptr[i + 1];
    int p = beg;
    for (; p + 4 <= end; p += 4) {
        int s0 = colsrc[p], s1 = colsrc[p + 1], s2 = colsrc[p + 2], s3 = colsrc[p + 3];
        float w_0 = wexp[(p + 0) * H + head];
        float w_1 = wexp[(p + 1) * H + head];
        float w_2 = wexp[(p + 2) * H + head];
        float w_3 = wexp[(p + 3) * H + head];
        float4 h0 = hfeat4[(size_t)s0 * 64 + tid];
        float4 h1 = hfeat4[(size_t)s1 * 64 + tid];
        float4 h2 = hfeat4[(size_t)s2 * 64 + tid];
        float4 h3 = hfeat4[(size_t)s3 * 64 + tid];
        den += (w_0 + w_1) + (w_2 + w_3);
        acc.x += w_0 * h0.x + w_1 * h1.x + w_2 * h2.x + w_3 * h3.x;
        acc.y += w_0 * h0.y + w_1 * h1.y + w_2 * h2.y + w_3 * h3.y;
        acc.z += w_0 * h0.z + w_1 * h1.z + w_2 * h2.z + w_3 * h3.z;
        acc.w += w_0 * h0.w + w_1 * h1.w + w_2 * h2.w + w_3 * h3.w;
    }
    for (; p < end; p++) {
        int s0 = colsrc[p];
        float wv = wexp[p * H + head];
        float4 h0 = hfeat4[(size_t)s0 * 64 + tid];
        den += wv;
        acc.x += wv * h0.x; acc.y += wv * h0.y; acc.z += wv * h0.z; acc.w += wv * h0.w;
    }

    float4 bv = bias4[tid];
    float inv = 1.f / den;
    float4 v = make_float4(acc.x * inv + bv.x, acc.y * inv + bv.y,
                           acc.z * inv + bv.z, acc.w * inv + bv.w);

    float mean = block_sum64(v.x + v.y + v.z + v.w, red) * (1.f / NF);
    float4 dl = make_float4(v.x - mean, v.y - mean, v.z - mean, v.w - mean);
    float var = block_sum64(dl.x * dl.x + dl.y * dl.y + dl.z * dl.z + dl.w * dl.w, red)
                * (1.f / NF);
    float rs = rsqrtf(var + 1e-5f);
    float4 wv4 = lnw4[tid];
    float4 bb = lnb4[tid];
    float4 y;
    y.x = dl.x * rs * wv4.x + bb.x;
    y.y = dl.y * rs * wv4.y + bb.y;
    y.z = dl.z * rs * wv4.z + bb.z;
    y.w = dl.w * rs * wv4.w + bb.w;
    y.x = y.x > 0.f ? y.x : expm1f(y.x);
    y.y = y.y > 0.f ? y.y : expm1f(y.y);
    y.z = y.z > 0.f ? y.z : expm1f(y.z);
    y.w = y.w > 0.f ? y.w : expm1f(y.w);

    if (SPLIT) {
        uint2 hi, lo;
        hi.x = bf16_pack_hi(y.x, y.y);
        hi.y = bf16_pack_hi(y.z, y.w);
        lo.x = bf16_pack_lo(y.x, y.y);
        lo.y = bf16_pack_lo(y.z, y.w);
        *(uint2*)(yh + (size_t)i * 128 + 2 * tid) = hi;
        *(uint2*)(yl + (size_t)i * 128 + 2 * tid) = lo;
    } else {
        out4[(size_t)i * 64 + tid] = y;
    }
}

// ---------------- launch ----------------------------------------------------
extern "C" void kernel_launch(void* const* d_in, const int* in_sizes, int n_in,
                              void* d_out, int out_size) {
    const float* x    = (const float*)d_in[0];
    const int*   ei   = (const int*)d_in[1];
    const float* W0   = (const float*)d_in[2];
    const float* as0  = (const float*)d_in[3];
    const float* ad0  = (const float*)d_in[4];
    const float* b0   = (const float*)d_in[5];
    const float* lnw0 = (const float*)d_in[6];
    const float* lnb0 = (const float*)d_in[7];
    const float* W1   = (const float*)d_in[8];
    const float* as1  = (const float*)d_in[9];
    const float* ad1  = (const float*)d_in[10];
    const float* b1   = (const float*)d_in[11];
    const float* lnw1 = (const float*)d_in[12];
    const float* lnb1 = (const float*)d_in[13];
    const float* W2   = (const float*)d_in[14];
    const float* as2  = (const float*)d_in[15];
    const float* ad2  = (const float*)d_in[16];
    const float* b2   = (const float*)d_in[17];
    const float* lnw2 = (const float*)d_in[18];
    const float* lnb2 = (const float*)d_in[19];
    float* out = (float*)d_out;

    int n = in_sizes[0] / 512;   // 50000
    int e = in_sizes[1] / 2;     // 800000
    const int* src = ei;
    const int* dst = ei + e;

    float *ph, *palpha, *pwexp;
    int *pcnt, *prow, *pcur, *pcol, *pcds;
    uint32_t *pxh, *pxl, *pyh, *pyl;
    uint32_t *pw0h, *pw0l, *pw1h, *pw1l, *pw2h, *pw2l;
    cudaGetSymbolAddress((void**)&ph, g_h);
    cudaGetSymbolAddress((void**)&palpha, g_alpha);
    cudaGetSymbolAddress((void**)&pwexp, g_wexp);
    cudaGetSymbolAddress((void**)&pcnt, g_cnt);
    cudaGetSymbolAddress((void**)&prow, g_rowptr);
    cudaGetSymbolAddress((void**)&pcur, g_cursor);
    cudaGetSymbolAddress((void**)&pcol, g_colsrc);
    cudaGetSymbolAddress((void**)&pcds, g_coldst);
    cudaGetSymbolAddress((void**)&pxh, g_xh);
    cudaGetSymbolAddress((void**)&pxl, g_xl);
    cudaGetSymbolAddress((void**)&pyh, g_yh);
    cudaGetSymbolAddress((void**)&pyl, g_yl);
    cudaGetSymbolAddress((void**)&pw0h, g_w0h);
    cudaGetSymbolAddress((void**)&pw0l, g_w0l);
    cudaGetSymbolAddress((void**)&pw1h, g_w1h);
    cudaGetSymbolAddress((void**)&pw1l, g_w1l);
    cudaGetSymbolAddress((void**)&pw2h, g_w2h);
    cudaGetSymbolAddress((void**)&pw2l, g_w2l);

    float* pas0 = palpha + (size_t)0 * MAXN * 4;
    float* pad0 = palpha + (size_t)1 * MAXN * 4;
    float* pas1 = palpha + (size_t)2 * MAXN * 4;
    float* pad1 = palpha + (size_t)3 * MAXN * 4;
    float* pas2 = palpha + (size_t)4 * MAXN * 4;
    float* pad2 = palpha + (size_t)5 * MAXN * 4;

    cudaFuncSetAttribute(gemm_bf16<4>, cudaFuncAttributeMaxDynamicSharedMemorySize, GSMEM);
    cudaFuncSetAttribute(gemm_bf16<1>, cudaFuncAttributeMaxDynamicSharedMemorySize, GSMEM);

    const int TPB = 256;
    const int egrid = (e + TPB - 1) / TPB;
    const int xtotal = n * 256;

    hist_kernel<<<egrid, TPB>>>(dst, pcnt, e, palpha, W0, W1, W2,
                                pw0h, pw0l, pw1h, pw1l, pw2h, pw2l,
                                (const float2*)x, pxh, pxl, xtotal);
    scan_kernel<<<1, 1024>>>(pcnt, prow, pcur, n);
    scatter_kernel<<<egrid, TPB>>>(src, dst, pcur, pcol, pcds, e);

    dim3 ggrid(NF / 128, (n + 127) / 128);

    // layer 0: GATConv(512 -> 4x64)
    gemm_bf16<4><<<ggrid, 256, GSMEM>>>(pxh, pxl, pw0h, pw0l, ph, n, 512,
                                        as0, ad0, pas0, pad0);
    weight_kernel<4><<<egrid, TPB>>>(pas0, pad0, pcol, pcds, pwexp, e);
    agg_kernel<4, true><<<n, 64>>>((const float4*)ph, pas0, pad0, prow, pcol, pwexp,
                                   (const float4*)b0, (const float4*)lnw0,
                                   (const float4*)lnb0, nullptr, pyh, pyl);

    // layer 1: GATConv(256 -> 4x64)
    gemm_bf16<4><<<ggrid, 256, GSMEM>>>(pyh, pyl, pw1h, pw1l, ph, n, 256,
                                        as1, ad1, pas1, pad1);
    weight_kernel<4><<<egrid, TPB>>>(pas1, pad1, pcol, pcds, pwexp, e);
    agg_kernel<4, true><<<n, 64>>>((const float4*)ph, pas1, pad1, prow, pcol, pwexp,
                                   (const float4*)b1, (const float4*)lnw1,
                                   (const float4*)lnb1, nullptr, pyh, pyl);

    // layer 2: GATConv(256 -> 1x256)
    gemm_bf16<1><<<ggrid, 256, GSMEM>>>(pyh, pyl, pw2h, pw2l, ph, n, 256,
                                        as2, ad2, pas2, pad2);
    weight_kernel<1><<<egrid, TPB>>>(pas2, pad2, pcol, pcds, pwexp, e);
    agg_kernel<1, false><<<n, 64>>>((const float4*)ph, pas2, pad2, prow, pcol, pwexp,
                                    (const float4*)b2, (const float4*)lnw2,
                                    (const float4*)lnb2, (float4*)out, nullptr, nullptr);
}

// round 17
// speedup vs baseline: 1.4450x; 1.1875x over previous
#include <cuda_runtime.h>
#include <cuda_bf16.h>
#include <stdint.h>
#include <math.h>

#define MAXN 50000
#define MAXE 800000
#define NF 256

// ---------------- scratch (device globals; no allocation allowed) ----------
__device__ float g_h[(size_t)MAXN * NF];     // GEMM fp32 output (for agg gather)
__device__ float g_alpha[(size_t)6 * MAXN * 4];
__device__ float g_wexp[(size_t)MAXE * 4];
__device__ int   g_cnt[MAXN];
__device__ int   g_rowptr[MAXN + 1];
__device__ int   g_cursor[MAXN];
__device__ int   g_colsrc[MAXE];
__device__ int   g_coldst[MAXE];
// pre-split activations: [row][kpair] packed bf16x2
__device__ uint32_t g_xh[(size_t)MAXN * 256], g_xl[(size_t)MAXN * 256];   // x: K=512
__device__ uint32_t g_yh[(size_t)MAXN * 128], g_yl[(size_t)MAXN * 128];   // layer outs
// pre-transposed, bf16-split weights: [n][kpair] packed bf16x2
__device__ uint32_t g_w0h[256 * 256], g_w0l[256 * 256];
__device__ uint32_t g_w1h[256 * 128], g_w1l[256 * 128];
__device__ uint32_t g_w2h[256 * 128], g_w2l[256 * 128];

// ---------------- bf16 split helpers ----------------------------------------
__device__ __forceinline__ uint32_t bf16_pack_hi(float f0, float f1) {
    __nv_bfloat16 h0 = __float2bfloat16(f0);
    __nv_bfloat16 h1 = __float2bfloat16(f1);
    return (uint32_t)__bfloat16_as_ushort(h0) | ((uint32_t)__bfloat16_as_ushort(h1) << 16);
}
__device__ __forceinline__ uint32_t bf16_pack_lo(float f0, float f1) {
    __nv_bfloat16 h0 = __float2bfloat16(f0);
    __nv_bfloat16 h1 = __float2bfloat16(f1);
    __nv_bfloat16 l0 = __float2bfloat16(f0 - __bfloat162float(h0));
    __nv_bfloat16 l1 = __float2bfloat16(f1 - __bfloat162float(h1));
    return (uint32_t)__bfloat16_as_ushort(l0) | ((uint32_t)__bfloat16_as_ushort(l1) << 16);
}

__device__ __forceinline__ void mma_bf16(float c[4],
                                         uint32_t a0, uint32_t a1, uint32_t a2, uint32_t a3,
                                         uint32_t b0, uint32_t b1) {
    asm volatile(
        "mma.sync.aligned.m16n8k16.row.col.f32.bf16.bf16.f32 "
        "{%0,%1,%2,%3}, {%4,%5,%6,%7}, {%8,%9}, {%0,%1,%2,%3};"
        : "+f"(c[0]), "+f"(c[1]), "+f"(c[2]), "+f"(c[3])
        : "r"(a0), "r"(a1), "r"(a2), "r"(a3), "r"(b0), "r"(b1));
}

__device__ __forceinline__ uint32_t smem_u32(const void* p) {
    uint32_t a;
    asm("{ .reg .u64 t; cvta.to.shared.u64 t, %1; cvt.u32.u64 %0, t; }" : "=r"(a) : "l"(p));
    return a;
}
__device__ __forceinline__ void cp16(uint32_t d, const uint32_t* s, bool p) {
    int sz = p ? 16 : 0;
    asm volatile("cp.async.cg.shared.global [%0], [%1], 16, %2;"
                 :: "r"(d), "l"(s), "r"(sz) : "memory");
}
#define CP_COMMIT() asm volatile("cp.async.commit_group;" ::: "memory")
#define CP_WAIT1()  asm volatile("cp.async.wait_group 1;" ::: "memory")

__device__ __forceinline__ void ldsm4(uint32_t a, uint32_t& r0, uint32_t& r1,
                                      uint32_t& r2, uint32_t& r3) {
    asm volatile("ldmatrix.sync.aligned.m8n8.x4.shared.b16 {%0,%1,%2,%3}, [%4];"
                 : "=r"(r0), "=r"(r1), "=r"(r2), "=r"(r3) : "r"(a));
}

// ---------------- prep: alpha zero + weight prep + x split (main stream) ----
__global__ void prep_kernel(float* __restrict__ alpha,
                            const float* __restrict__ W0, const float* __restrict__ W1,
                            const float* __restrict__ W2,
                            uint32_t* __restrict__ w0h, uint32_t* __restrict__ w0l,
                            uint32_t* __restrict__ w1h, uint32_t* __restrict__ w1l,
                            uint32_t* __restrict__ w2h, uint32_t* __restrict__ w2l,
                            const float2* __restrict__ x2,
                            uint32_t* __restrict__ xh, uint32_t* __restrict__ xl,
                            int xtotal) {
    int t = blockIdx.x * blockDim.x + threadIdx.x;
    int nthr = gridDim.x * blockDim.x;
    const int atot = 6 * MAXN * 4;
    for (int i = t; i < atot; i += nthr) alpha[i] = 0.f;
    const int T0 = 256 * 256, T1 = 256 * 128;
    if (t < T0) {
        int n = t >> 8, kp = t & 255;
        float f0 = W0[(2 * kp) * 256 + n];
        float f1 = W0[(2 * kp + 1) * 256 + n];
        w0h[n * 256 + kp] = bf16_pack_hi(f0, f1);
        w0l[n * 256 + kp] = bf16_pack_lo(f0, f1);
    } else if (t < T0 + T1) {
        int id = t - T0;
        int n = id >> 7, kp = id & 127;
        float f0 = W1[(2 * kp) * 256 + n];
        float f1 = W1[(2 * kp + 1) * 256 + n];
        w1h[n * 128 + kp] = bf16_pack_hi(f0, f1);
        w1l[n * 128 + kp] = bf16_pack_lo(f0, f1);
    } else if (t < T0 + 2 * T1) {
        int id = t - T0 - T1;
        int n = id >> 7, kp = id & 127;
        float f0 = W2[(2 * kp) * 256 + n];
        float f1 = W2[(2 * kp + 1) * 256 + n];
        w2h[n * 128 + kp] = bf16_pack_hi(f0, f1);
        w2l[n * 128 + kp] = bf16_pack_lo(f0, f1);
    }
    for (int i = t; i < xtotal; i += nthr) {
        float2 f = x2[i];
        xh[i] = bf16_pack_hi(f.x, f.y);
        xl[i] = bf16_pack_lo(f.x, f.y);
    }
}

// ---------------- CSR build (side stream, overlaps gemm0) -------------------
__global__ void hist_kernel(const int* __restrict__ dst, int* __restrict__ cnt, int e) {
    int t = blockIdx.x * blockDim.x + threadIdx.x;
    if (t < e) atomicAdd(&cnt[dst[t]], 1);
}

__global__ void scan_kernel(int* __restrict__ cnt, int* __restrict__ rowptr,
                            int* __restrict__ cursor, int n) {
    __shared__ int sh[1024];
    int tid = threadIdx.x;
    int chunk = (n + 1023) >> 10;
    int base = tid * chunk;
    int s = 0;
    for (int j = 0; j < chunk; j++) {
        int idx = base + j;
        if (idx < n) s += cnt[idx];
    }
    sh[tid] = s;
    __syncthreads();
    for (int off = 1; off < 1024; off <<= 1) {
        int v = (tid >= off) ? sh[tid - off] : 0;
        __syncthreads();
        sh[tid] += v;
        __syncthreads();
    }
    int run = sh[tid] - s;
    for (int j = 0; j < chunk; j++) {
        int idx = base + j;
        if (idx < n) {
            rowptr[idx] = run;
            cursor[idx] = run;
            run += cnt[idx];
            cnt[idx] = 0;
        }
    }
    if (tid == 1023) rowptr[n] = run;
}

__global__ void scatter_kernel(const int* __restrict__ src, const int* __restrict__ dst,
                               int* __restrict__ cursor, int* __restrict__ colsrc,
                               int* __restrict__ coldst, int e) {
    int t = blockIdx.x * blockDim.x + threadIdx.x;
    if (t < e) {
        int d = dst[t];
        int p = atomicAdd(&cursor[d], 1);
        colsrc[p] = src[t];
        coldst[p] = d;
    }
}

// ---------------- per-edge softmax numerators --------------------------------
template <int H>
__global__ void weight_kernel(const float* __restrict__ asrc, const float* __restrict__ adst,
                              const int* __restrict__ colsrc, const int* __restrict__ coldst,
                              float* __restrict__ wexp, int e) {
    int t = blockIdx.x * blockDim.x + threadIdx.x;
    if (t < e) {
        int s = colsrc[t], d = coldst[t];
#pragma unroll
        for (int h = 0; h < H; h++) {
            float ev = asrc[s * H + h] + adst[d * H + h];
            ev = ev > 0.f ? ev : 0.2f * ev;
            wexp[t * H + h] = __expf(ev);
        }
    }
}

// ---------------- cp.async triple-buffered bf16x3 GEMM (ldmatrix frags) -----
#define ARRW  2048                 // 128 rows x 16 words
#define SLOTW (4 * ARRW)
#define GSMEM (3 * SLOTW * 4)      // 98304 B

template <int H>
__global__ void __launch_bounds__(256, 2) gemm_bf16(
    const uint32_t* __restrict__ Ath, const uint32_t* __restrict__ Atl,
    const uint32_t* __restrict__ Bth, const uint32_t* __restrict__ Btl,
    float* __restrict__ C, int M, int K,
    const float* __restrict__ a_s, const float* __restrict__ a_d,
    float* __restrict__ asrc, float* __restrict__ adst)
{
    extern __shared__ uint32_t sm[];
    const uint32_t smb = smem_u32(sm);

    const int tid  = threadIdx.x;
    const int lane = tid & 31;
    const int w    = tid >> 5;
    const int g    = lane >> 2;
    const int t    = lane & 3;
    const int wm   = w >> 2;
    const int wn   = w & 3;

    const int row0 = blockIdx.y * 128;
    const int col0 = blockIdx.x * 128;
    const int KW   = K >> 1;
    const int NSUP = K >> 5;

    const int r  = tid >> 1;
    const int hh = tid & 1;
    const int rq = (r >> 1) & 3;
    const bool aok = (row0 + r) < M;
    const int arow = aok ? (row0 + r) : (M - 1);
    const uint32_t* gAh = Ath + (size_t)arow * KW;
    const uint32_t* gAl = Atl + (size_t)arow * KW;
    const uint32_t* gBh = Bth + (size_t)(col0 + r) * KW;
    const uint32_t* gBl = Btl + (size_t)(col0 + r) * KW;
    const int c0 = 2 * hh, c1 = 2 * hh + 1;
    const uint32_t d0 = smb + (uint32_t)(r * 16 + ((c0 ^ rq) << 2)) * 4;
    const uint32_t d1 = smb + (uint32_t)(r * 16 + ((c1 ^ rq) << 2)) * 4;

    const int lrowA  = lane & 15;
    const int lhalfA = lane >> 4;
    const int lrowB  = lane & 7;
    const int lselB  = (lane >> 3) & 1;
    const int lntB   = lane >> 4;

    float acc[4][4][4];
#pragma unroll
    for (int mt = 0; mt < 4; mt++)
#pragma unroll
        for (int nt = 0; nt < 4; nt++)
#pragma unroll
            for (int i = 0; i < 4; i++) acc[mt][nt][i] = 0.f;

#pragma unroll
    for (int s = 0; s < 2; s++) {
        uint32_t so = (uint32_t)(s * SLOTW) * 4;
        int kp0 = s * 16 + c0 * 4;
        int kp1 = s * 16 + c1 * 4;
        cp16(d0 + so,                gAh + kp0, aok);
        cp16(d1 + so,                gAh + kp1, aok);
        cp16(d0 + so + ARRW * 4,     gAl + kp0, aok);
        cp16(d1 + so + ARRW * 4,     gAl + kp1, aok);
        cp16(d0 + so + 2 * ARRW * 4, gBh + kp0, true);
        cp16(d1 + so + 2 * ARRW * 4, gBh + kp1, true);
        cp16(d0 + so + 3 * ARRW * 4, gBl + kp0, true);
        cp16(d1 + so + 3 * ARRW * 4, gBl + kp1, true);
        CP_COMMIT();
    }

    int slot = 0, nslot = 2;
    for (int p = 0; p < NSUP; p++) {
        CP_WAIT1();
        __syncthreads();

        int nx = p + 2;
        if (nx < NSUP) {
            uint32_t so = (uint32_t)(nslot * SLOTW) * 4;
            int kp0 = nx * 16 + c0 * 4;
            int kp1 = nx * 16 + c1 * 4;
            cp16(d0 + so,                gAh + kp0, aok);
            cp16(d1 + so,                gAh + kp1, aok);
            cp16(d0 + so + ARRW * 4,     gAl + kp0, aok);
            cp16(d1 + so + ARRW * 4,     gAl + kp1, aok);
            cp16(d0 + so + 2 * ARRW * 4, gBh + kp0, true);
            cp16(d1 + so + 2 * ARRW * 4, gBh + kp1, true);
            cp16(d0 + so + 3 * ARRW * 4, gBl + kp0, true);
            cp16(d1 + so + 3 * ARRW * 4, gBl + kp1, true);
        }
        CP_COMMIT();

        const uint32_t sb_slot = smb + (uint32_t)(slot * SLOTW) * 4;
        const uint32_t baseAh = sb_slot;
        const uint32_t baseAl = sb_slot + ARRW * 4;
        const uint32_t baseBh = sb_slot + 2 * ARRW * 4;
        const uint32_t baseBl = sb_slot + 3 * ARRW * 4;
#pragma unroll
        for (int kk = 0; kk < 2; kk++) {
            uint32_t bh[4][2], bl[4][2];
#pragma unroll
            for (int j = 0; j < 4; j += 2) {
                int n = wn * 32 + (j + lntB) * 8 + lrowB;
                int c = 2 * kk + lselB;
                int q = (n >> 1) & 3;
                uint32_t off = (uint32_t)(n * 16 + ((c ^ q) << 2)) * 4;
                ldsm4(baseBh + off, bh[j][0], bh[j][1], bh[j + 1][0], bh[j + 1][1]);
                ldsm4(baseBl + off, bl[j][0], bl[j][1], bl[j + 1][0], bl[j + 1][1]);
            }
#pragma unroll
            for (int mt = 0; mt < 4; mt++) {
                int rowA = wm * 64 + mt * 16 + lrowA;
                int cA = 2 * kk + lhalfA;
                int qA = (rowA >> 1) & 3;
                uint32_t offA = (uint32_t)(rowA * 16 + ((cA ^ qA) << 2)) * 4;
                uint32_t ah[4], al[4];
                ldsm4(baseAh + offA, ah[0], ah[1], ah[2], ah[3]);
                ldsm4(baseAl + offA, al[0], al[1], al[2], al[3]);
#pragma unroll
                for (int nt = 0; nt < 4; nt++)
                    mma_bf16(acc[mt][nt], ah[0], ah[1], ah[2], ah[3], bh[nt][0], bh[nt][1]);
#pragma unroll
                for (int nt = 0; nt < 4; nt++)
                    mma_bf16(acc[mt][nt], ah[0], ah[1], ah[2], ah[3], bl[nt][0], bl[nt][1]);
#pragma unroll
                for (int nt = 0; nt < 4; nt++)
                    mma_bf16(acc[mt][nt], al[0], al[1], al[2], al[3], bh[nt][0], bh[nt][1]);
            }
        }
        slot = (slot == 2) ? 0 : slot + 1;
        nslot = (nslot == 2) ? 0 : nslot + 1;
    }

    // ---- epilogue 1: store C tile ----
#pragma unroll
    for (int mt = 0; mt < 4; mt++) {
        int r0 = row0 + wm * 64 + mt * 16 + g;
        int r1 = r0 + 8;
#pragma unroll
        for (int nt = 0; nt < 4; nt++) {
            int col = col0 + wn * 32 + nt * 8 + 2 * t;
            if (r0 < M)
                *(float2*)(C + (size_t)r0 * NF + col) = make_float2(acc[mt][nt][0], acc[mt][nt][1]);
            if (r1 < M)
                *(float2*)(C + (size_t)r1 * NF + col) = make_float2(acc[mt][nt][2], acc[mt][nt][3]);
        }
    }

    // ---- epilogue 2: fused alpha projection (atomic; zeroed by prep) -------
    {
        float asv[4][2], adv[4][2];
#pragma unroll
        for (int nt = 0; nt < 4; nt++)
#pragma unroll
            for (int i = 0; i < 2; i++) {
                int gcol = col0 + wn * 32 + nt * 8 + 2 * t + i;
                asv[nt][i] = a_s[gcol];
                adv[nt][i] = a_d[gcol];
            }
        const int hd = (H == 4) ? ((col0 + wn * 32) >> 6) : 0;
#pragma unroll
        for (int mt = 0; mt < 4; mt++) {
            float sa0 = 0.f, sd0 = 0.f, sa1 = 0.f, sd1 = 0.f;
#pragma unroll
            for (int nt = 0; nt < 4; nt++)
#pragma unroll
                for (int i = 0; i < 2; i++) {
                    sa0 += acc[mt][nt][i]     * asv[nt][i];
                    sd0 += acc[mt][nt][i]     * adv[nt][i];
                    sa1 += acc[mt][nt][2 + i] * asv[nt][i];
                    sd1 += acc[mt][nt][2 + i] * adv[nt][i];
                }
#pragma unroll
            for (int o = 1; o <= 2; o <<= 1) {
                sa0 += __shfl_xor_sync(0xffffffffu, sa0, o);
                sd0 += __shfl_xor_sync(0xffffffffu, sd0, o);
                sa1 += __shfl_xor_sync(0xffffffffu, sa1, o);
                sd1 += __shfl_xor_sync(0xffffffffu, sd1, o);
            }
            if (t == 0) {
                int r0 = row0 + wm * 64 + mt * 16 + g;
                int r1 = r0 + 8;
                if (r0 < M) {
                    atomicAdd(&asrc[r0 * H + hd], sa0);
                    atomicAdd(&adst[r0 * H + hd], sd0);
                }
                if (r1 < M) {
                    atomicAdd(&asrc[r1 * H + hd], sa1);
                    atomicAdd(&adst[r1 * H + hd], sd1);
                }
            }
        }
    }
}

// ---------------- block-sum helper (64 threads, 2 warps) ---------------------
__device__ __forceinline__ float block_sum64(float v, float* red) {
#pragma unroll
    for (int o = 16; o > 0; o >>= 1) v += __shfl_xor_sync(0xffffffffu, v, o);
    int wid = threadIdx.x >> 5;
    if ((threadIdx.x & 31) == 0) red[wid] = v;
    __syncthreads();
    float s = red[0] + red[1];
    __syncthreads();
    return s;
}

// ---------------- fused aggregation + bias + LN + ELU -----------------------
template <int H, bool SPLIT>
__global__ void __launch_bounds__(64) agg_kernel(
    const float4* __restrict__ hfeat4,
    const float* __restrict__ asrc, const float* __restrict__ adst,
    const int* __restrict__ rowptr, const int* __restrict__ colsrc,
    const float* __restrict__ wexp,
    const float4* __restrict__ bias4, const float4* __restrict__ lnw4,
    const float4* __restrict__ lnb4,
    float4* __restrict__ out4,
    uint32_t* __restrict__ yh, uint32_t* __restrict__ yl)
{
    __shared__ float red[2];

    int i   = blockIdx.x;
    int tid = threadIdx.x;
    int head = (H == 4) ? (tid >> 4) : 0;

    float e0 = asrc[i * H + head] + adst[i * H + head];
    e0 = e0 > 0.f ? e0 : 0.2f * e0;
    float w0 = __expf(e0);
    float den = w0;
    float4 hv = hfeat4[(size_t)i * 64 + tid];
    float4 acc = make_float4(w0 * hv.x, w0 * hv.y, w0 * hv.z, w0 * hv.w);

    int beg = rowptr[i], end = rowptr[i + 1];
    int p = beg;
    for (; p + 4 <= end; p += 4) {
        int s0 = colsrc[p], s1 = colsrc[p + 1], s2 = colsrc[p + 2], s3 = colsrc[p + 3];
        float w_0 = wexp[(p + 0) * H + head];
        float w_1 = wexp[(p + 1) * H + head];
        float w_2 = wexp[(p + 2) * H + head];
        float w_3 = wexp[(p + 3) * H + head];
        float4 h0 = hfeat4[(size_t)s0 * 64 + tid];
        float4 h1 = hfeat4[(size_t)s1 * 64 + tid];
        float4 h2 = hfeat4[(size_t)s2 * 64 + tid];
        float4 h3 = hfeat4[(size_t)s3 * 64 + tid];
        den += (w_0 + w_1) + (w_2 + w_3);
        acc.x += w_0 * h0.x + w_1 * h1.x + w_2 * h2.x + w_3 * h3.x;
        acc.y += w_0 * h0.y + w_1 * h1.y + w_2 * h2.y + w_3 * h3.y;
        acc.z += w_0 * h0.z + w_1 * h1.z + w_2 * h2.z + w_3 * h3.z;
        acc.w += w_0 * h0.w + w_1 * h1.w + w_2 * h2.w + w_3 * h3.w;
    }
    for (; p < end; p++) {
        int s0 = colsrc[p];
        float wv = wexp[p * H + head];
        float4 h0 = hfeat4[(size_t)s0 * 64 + tid];
        den += wv;
        acc.x += wv * h0.x; acc.y += wv * h0.y; acc.z += wv * h0.z; acc.w += wv * h0.w;
    }

    float4 bv = bias4[tid];
    float inv = 1.f / den;
    float4 v = make_float4(acc.x * inv + bv.x, acc.y * inv + bv.y,
                           acc.z * inv + bv.z, acc.w * inv + bv.w);

    float mean = block_sum64(v.x + v.y + v.z + v.w, red) * (1.f / NF);
    float4 dl = make_float4(v.x - mean, v.y - mean, v.z - mean, v.w - mean);
    float var = block_sum64(dl.x * dl.x + dl.y * dl.y + dl.z * dl.z + dl.w * dl.w, red)
                * (1.f / NF);
    float rs = rsqrtf(var + 1e-5f);
    float4 wv4 = lnw4[tid];
    float4 bb = lnb4[tid];
    float4 y;
    y.x = dl.x * rs * wv4.x + bb.x;
    y.y = dl.y * rs * wv4.y + bb.y;
    y.z = dl.z * rs * wv4.z + bb.z;
    y.w = dl.w * rs * wv4.w + bb.w;
    y.x = y.x > 0.f ? y.x : expm1f(y.x);
    y.y = y.y > 0.f ? y.y : expm1f(y.y);
    y.z = y.z > 0.f ? y.z : expm1f(y.z);
    y.w = y.w > 0.f ? y.w : expm1f(y.w);

    if (SPLIT) {
        uint2 hi, lo;
        hi.x = bf16_pack_hi(y.x, y.y);
        hi.y = bf16_pack_hi(y.z, y.w);
        lo.x = bf16_pack_lo(y.x, y.y);
        lo.y = bf16_pack_lo(y.z, y.w);
        *(uint2*)(yh + (size_t)i * 128 + 2 * tid) = hi;
        *(uint2*)(yl + (size_t)i * 128 + 2 * tid) = lo;
    } else {
        out4[(size_t)i * 64 + tid] = y;
    }
}

// ---------------- launch ----------------------------------------------------
extern "C" void kernel_launch(void* const* d_in, const int* in_sizes, int n_in,
                              void* d_out, int out_size) {
    const float* x    = (const float*)d_in[0];
    const int*   ei   = (const int*)d_in[1];
    const float* W0   = (const float*)d_in[2];
    const float* as0  = (const float*)d_in[3];
    const float* ad0  = (const float*)d_in[4];
    const float* b0   = (const float*)d_in[5];
    const float* lnw0 = (const float*)d_in[6];
    const float* lnb0 = (const float*)d_in[7];
    const float* W1   = (const float*)d_in[8];
    const float* as1  = (const float*)d_in[9];
    const float* ad1  = (const float*)d_in[10];
    const float* b1   = (const float*)d_in[11];
    const float* lnw1 = (const float*)d_in[12];
    const float* lnb1 = (const float*)d_in[13];
    const float* W2   = (const float*)d_in[14];
    const float* as2  = (const float*)d_in[15];
    const float* ad2  = (const float*)d_in[16];
    const float* b2   = (const float*)d_in[17];
    const float* lnw2 = (const float*)d_in[18];
    const float* lnb2 = (const float*)d_in[19];
    float* out = (float*)d_out;

    int n = in_sizes[0] / 512;   // 50000
    int e = in_sizes[1] / 2;     // 800000
    const int* src = ei;
    const int* dst = ei + e;

    float *ph, *palpha, *pwexp;
    int *pcnt, *prow, *pcur, *pcol, *pcds;
    uint32_t *pxh, *pxl, *pyh, *pyl;
    uint32_t *pw0h, *pw0l, *pw1h, *pw1l, *pw2h, *pw2l;
    cudaGetSymbolAddress((void**)&ph, g_h);
    cudaGetSymbolAddress((void**)&palpha, g_alpha);
    cudaGetSymbolAddress((void**)&pwexp, g_wexp);
    cudaGetSymbolAddress((void**)&pcnt, g_cnt);
    cudaGetSymbolAddress((void**)&prow, g_rowptr);
    cudaGetSymbolAddress((void**)&pcur, g_cursor);
    cudaGetSymbolAddress((void**)&pcol, g_colsrc);
    cudaGetSymbolAddress((void**)&pcds, g_coldst);
    cudaGetSymbolAddress((void**)&pxh, g_xh);
    cudaGetSymbolAddress((void**)&pxl, g_xl);
    cudaGetSymbolAddress((void**)&pyh, g_yh);
    cudaGetSymbolAddress((void**)&pyl, g_yl);
    cudaGetSymbolAddress((void**)&pw0h, g_w0h);
    cudaGetSymbolAddress((void**)&pw0l, g_w0l);
    cudaGetSymbolAddress((void**)&pw1h, g_w1h);
    cudaGetSymbolAddress((void**)&pw1l, g_w1l);
    cudaGetSymbolAddress((void**)&pw2h, g_w2h);
    cudaGetSymbolAddress((void**)&pw2l, g_w2l);

    float* pas0 = palpha + (size_t)0 * MAXN * 4;
    float* pad0 = palpha + (size_t)1 * MAXN * 4;
    float* pas1 = palpha + (size_t)2 * MAXN * 4;
    float* pad1 = palpha + (size_t)3 * MAXN * 4;
    float* pas2 = palpha + (size_t)4 * MAXN * 4;
    float* pad2 = palpha + (size_t)5 * MAXN * 4;

    cudaFuncSetAttribute(gemm_bf16<4>, cudaFuncAttributeMaxDynamicSharedMemorySize, GSMEM);
    cudaFuncSetAttribute(gemm_bf16<1>, cudaFuncAttributeMaxDynamicSharedMemorySize, GSMEM);

    // one-time side stream + fork/join events (created on the uncaptured
    // correctness call; reused identically on every capture/replay)
    static cudaStream_t s_side = nullptr;
    static cudaEvent_t  s_fork = nullptr, s_join = nullptr;
    if (!s_side) {
        cudaStreamCreateWithFlags(&s_side, cudaStreamNonBlocking);
        cudaEventCreateWithFlags(&s_fork, cudaEventDisableTiming);
        cudaEventCreateWithFlags(&s_join, cudaEventDisableTiming);
    }

    const int TPB = 256;
    const int egrid = (e + TPB - 1) / TPB;
    const int xtotal = n * 256;

    // fork: CSR build runs on the side stream, overlapping prep + gemm0
    cudaEventRecord(s_fork, 0);
    cudaStreamWaitEvent(s_side, s_fork, 0);
    hist_kernel<<<egrid, TPB, 0, s_side>>>(dst, pcnt, e);
    scan_kernel<<<1, 1024, 0, s_side>>>(pcnt, prow, pcur, n);
    scatter_kernel<<<egrid, TPB, 0, s_side>>>(src, dst, pcur, pcol, pcds, e);
    cudaEventRecord(s_join, s_side);

    // main stream: prep (needed by gemm0) then gemm0
    prep_kernel<<<egrid, TPB>>>(palpha, W0, W1, W2,
                                pw0h, pw0l, pw1h, pw1l, pw2h, pw2l,
                                (const float2*)x, pxh, pxl, xtotal);

    dim3 ggrid(NF / 128, (n + 127) / 128);

    // layer 0: GATConv(512 -> 4x64)
    gemm_bf16<4><<<ggrid, 256, GSMEM>>>(pxh, pxl, pw0h, pw0l, ph, n, 512,
                                        as0, ad0, pas0, pad0);
    // join: weight/agg need the CSR
    cudaStreamWaitEvent(0, s_join, 0);
    weight_kernel<4><<<egrid, TPB>>>(pas0, pad0, pcol, pcds, pwexp, e);
    agg_kernel<4, true><<<n, 64>>>((const float4*)ph, pas0, pad0, prow, pcol, pwexp,
                                   (const float4*)b0, (const float4*)lnw0,
                                   (const float4*)lnb0, nullptr, pyh, pyl);

    // layer 1: GATConv(256 -> 4x64)
    gemm_bf16<4><<<ggrid, 256, GSMEM>>>(pyh, pyl, pw1h, pw1l, ph, n, 256,
                                        as1, ad1, pas1, pad1);
    weight_kernel<4><<<egrid, TPB>>>(pas1, pad1, pcol, pcds, pwexp, e);
    agg_kernel<4, true><<<n, 64>>>((const float4*)ph, pas1, pad1, prow, pcol, pwexp,
                                   (const float4*)b1, (const float4*)lnw1,
                                   (const float4*)lnb1, nullptr, pyh, pyl);

    // layer 2: GATConv(256 -> 1x256)
    gemm_bf16<1><<<ggrid, 256, GSMEM>>>(pyh, pyl, pw2h, pw2l, ph, n, 256,
                                        as2, ad2, pas2, pad2);
    weight_kernel<1><<<egrid, TPB>>>(pas2, pad2, pcol, pcds, pwexp, e);
    agg_kernel<1, false><<<n, 64>>>((const float4*)ph, pas2, pad2, prow, pcol, pwexp,
                                    (const float4*)b2, (const float4*)lnw2,
                                    (const float4*)lnb2, (float4*)out, nullptr, nullptr);
}